// round 11
// baseline (speedup 1.0000x reference)
#include <cuda_runtime.h>
#include <cuda_bf16.h>
#include <cstdint>

typedef unsigned long long ull;

// Problem constants
#define BB   2
#define SS   2048
#define PP   1024
#define DD   2048
#define HH   16
#define DH   128
#define PSL  3072          // P + S
#define MM   4096          // B * S
#define LKS  8             // lora split-K factor

// ---------------------------------------------------------------------------
// Scratch (device globals; no allocation allowed in kernel_launch)
// ---------------------------------------------------------------------------
__device__ float g_attn[(size_t)MM * DD];             // [m, h*DH+d] fp32
__device__ float g_lqkv_part[LKS][(size_t)MM * 48];   // lora down partials (q|k|v)
__device__ float g_lo_part[LKS][(size_t)MM * 16];

// bf16 split operands
__device__ __nv_bfloat16 g_xhi[(size_t)MM * DD];
__device__ __nv_bfloat16 g_xlo[(size_t)MM * DD];
__device__ __nv_bfloat16 g_ahi[(size_t)MM * DD];
__device__ __nv_bfloat16 g_alo[(size_t)MM * DD];
__device__ __nv_bfloat16 g_whi[(size_t)4 * DD * DD];  // wq|wk|wv|wo
__device__ __nv_bfloat16 g_wlo[(size_t)4 * DD * DD];

// attention operands, bf16 hi/lo split
__device__ __nv_bfloat16 g_Qh[(size_t)BB * HH * SS * DH];   // [b,h,s,d] (pre-scaled)
__device__ __nv_bfloat16 g_Ql[(size_t)BB * HH * SS * DH];
__device__ __nv_bfloat16 g_Kh[(size_t)BB * HH * PSL * DH];  // [b,h,j,d]
__device__ __nv_bfloat16 g_Kl[(size_t)BB * HH * PSL * DH];
__device__ __nv_bfloat16 g_Vh[(size_t)BB * HH * PSL * DH];  // [b,h,j,d]
__device__ __nv_bfloat16 g_Vl[(size_t)BB * HH * PSL * DH];

// ---------------------------------------------------------------------------
// helpers
// ---------------------------------------------------------------------------
__device__ __forceinline__ uint32_t smem_to_u32(const void* smem_ptr) {
    uint32_t addr;
    asm("{ .reg .u64 tmp; cvta.to.shared.u64 tmp, %1; cvt.u32.u64 %0, tmp; }"
        : "=r"(addr) : "l"(smem_ptr));
    return addr;
}
__device__ __forceinline__ void cp16(uint32_t dst, const void* src) {
    asm volatile("cp.async.cg.shared.global [%0], [%1], 16;"
                 :: "r"(dst), "l"(src) : "memory");
}
#define CP_COMMIT() asm volatile("cp.async.commit_group;" ::: "memory")
#define CP_WAIT1()  asm volatile("cp.async.wait_group 1;" ::: "memory")
#define CP_WAIT0()  asm volatile("cp.async.wait_group 0;" ::: "memory")

__device__ __forceinline__ void ldsm4(uint32_t a[4], uint32_t addr) {
    asm volatile("ldmatrix.sync.aligned.m8n8.x4.shared.b16 {%0,%1,%2,%3}, [%4];"
        : "=r"(a[0]), "=r"(a[1]), "=r"(a[2]), "=r"(a[3]) : "r"(addr));
}
__device__ __forceinline__ void ldsm4t(uint32_t a[4], uint32_t addr) {
    asm volatile("ldmatrix.sync.aligned.m8n8.x4.trans.shared.b16 {%0,%1,%2,%3}, [%4];"
        : "=r"(a[0]), "=r"(a[1]), "=r"(a[2]), "=r"(a[3]) : "r"(addr));
}
__device__ __forceinline__ void mma16816(float d[4], const uint32_t a[4],
                                         const uint32_t b[2]) {
    asm volatile(
        "mma.sync.aligned.m16n8k16.row.col.f32.bf16.bf16.f32 "
        "{%0,%1,%2,%3}, {%4,%5,%6,%7}, {%8,%9}, {%0,%1,%2,%3};"
        : "+f"(d[0]), "+f"(d[1]), "+f"(d[2]), "+f"(d[3])
        : "r"(a[0]), "r"(a[1]), "r"(a[2]), "r"(a[3]), "r"(b[0]), "r"(b[1]));
}
__device__ __forceinline__ float ex2f(float x) {
    float r; asm("ex2.approx.ftz.f32 %0, %1;" : "=f"(r) : "f"(x)); return r;
}

// Truncation-based split of two floats into packed bf16x2 hi (exact truncation)
// and lo (RN of residual). hi keeps a in low half, b in high half.
__device__ __forceinline__ void bfsplit2(float a, float b, uint32_t& h, uint32_t& l) {
    uint32_t ai = __float_as_uint(a), bi = __float_as_uint(b);
    h = __byte_perm(ai, bi, 0x7632);
    float ra = a - __uint_as_float(ai & 0xffff0000u);
    float rb = b - __uint_as_float(bi & 0xffff0000u);
    asm("cvt.rn.bf16x2.f32 %0, %1, %2;" : "=r"(l) : "f"(rb), "f"(ra));
}
// split-store 32 consecutive floats as bf16 hi/lo (dst 8B-aligned)
__device__ __forceinline__ void store32_split(const float* v,
                                              __nv_bfloat16* dh, __nv_bfloat16* dl) {
    uint32_t hs[16], ls[16];
#pragma unroll
    for (int j = 0; j < 16; j++) bfsplit2(v[2 * j], v[2 * j + 1], hs[j], ls[j]);
#pragma unroll
    for (int j = 0; j < 4; j++) {
        ((uint4*)dh)[j] = *(uint4*)&hs[j * 4];
        ((uint4*)dl)[j] = *(uint4*)&ls[j * 4];
    }
}

// ---------------------------------------------------------------------------
// fp32 -> bf16 hi/lo split kernels (x and weights)
// ---------------------------------------------------------------------------
__device__ __forceinline__ void bsplit4_store(float4 v, __nv_bfloat16* hi,
                                              __nv_bfloat16* lo, size_t i4)
{
    uint32_t h0, l0, h1, l1;
    bfsplit2(v.x, v.y, h0, l0);
    bfsplit2(v.z, v.w, h1, l1);
    ((uint2*)hi)[i4] = make_uint2(h0, h1);
    ((uint2*)lo)[i4] = make_uint2(l0, l1);
}

__global__ __launch_bounds__(256)
void split4(const float* __restrict__ src, __nv_bfloat16* __restrict__ hi,
            __nv_bfloat16* __restrict__ lo)
{
    size_t i = (size_t)blockIdx.x * 256 + threadIdx.x;
    float4 v = ((const float4*)src)[i];
    bsplit4_store(v, hi, lo, i);
}

__global__ __launch_bounds__(256)
void split_w4(const float* __restrict__ w0, const float* __restrict__ w1,
              const float* __restrict__ w2, const float* __restrict__ w3)
{
    const int z = blockIdx.z;
    const float* src = (z == 0) ? w0 : ((z == 1) ? w1 : ((z == 2) ? w2 : w3));
    __nv_bfloat16* hi = g_whi + (size_t)z * DD * DD;
    __nv_bfloat16* lo = g_wlo + (size_t)z * DD * DD;
    size_t i = (size_t)blockIdx.x * 256 + threadIdx.x;
    float4 v = ((const float4*)src)[i];
    bsplit4_store(v, hi, lo, i);
}

// ---------------------------------------------------------------------------
// LoRA down-projections: split-K=LKS, thread = 4 rows x 3 cols (qkv) / 4x1 (o)
// ---------------------------------------------------------------------------
__global__ __launch_bounds__(256)
void lora_down_qkv(const float* __restrict__ x,
                   const float* __restrict__ wqA,
                   const float* __restrict__ wkA,
                   const float* __restrict__ wvA)
{
    __shared__ float xs[32][68];
    __shared__ float ws[32][48];
    const int tid = threadIdx.x;
    const int m0  = blockIdx.x * 64;
    const int kq  = blockIdx.y;
    const int cg  = tid & 15;
    const int rg  = tid >> 4;
    const int KSEG = DD / LKS;            // 256

    float acc[4][3];
#pragma unroll
    for (int i = 0; i < 4; i++)
#pragma unroll
        for (int j = 0; j < 3; j++) acc[i][j] = 0.f;

    const int srow = tid >> 2, seg = tid & 3;
    for (int k0 = kq * KSEG; k0 < kq * KSEG + KSEG; k0 += 32) {
        const float* xp = &x[(size_t)(m0 + srow) * DD + k0 + seg * 8];
        float4 v0 = *(const float4*)xp;
        float4 v1 = *(const float4*)(xp + 4);
        const int sbk = seg * 8;
        xs[sbk + 0][srow] = v0.x; xs[sbk + 1][srow] = v0.y;
        xs[sbk + 2][srow] = v0.z; xs[sbk + 3][srow] = v0.w;
        xs[sbk + 4][srow] = v1.x; xs[sbk + 5][srow] = v1.y;
        xs[sbk + 6][srow] = v1.z; xs[sbk + 7][srow] = v1.w;
        for (int idx = tid; idx < 32 * 48; idx += 256) {
            int kk = idx / 48, c = idx % 48;
            const float* w = (c < 16) ? wqA : ((c < 32) ? wkA : wvA);
            ws[kk][c] = w[(size_t)(k0 + kk) * 16 + (c & 15)];
        }
        __syncthreads();
#pragma unroll
        for (int kk = 0; kk < 32; kk++) {
            float4 xv = *(const float4*)&xs[kk][rg * 4];
            float w0 = ws[kk][cg * 3 + 0];
            float w1 = ws[kk][cg * 3 + 1];
            float w2 = ws[kk][cg * 3 + 2];
            acc[0][0] += xv.x * w0; acc[0][1] += xv.x * w1; acc[0][2] += xv.x * w2;
            acc[1][0] += xv.y * w0; acc[1][1] += xv.y * w1; acc[1][2] += xv.y * w2;
            acc[2][0] += xv.z * w0; acc[2][1] += xv.z * w1; acc[2][2] += xv.z * w2;
            acc[3][0] += xv.w * w0; acc[3][1] += xv.w * w1; acc[3][2] += xv.w * w2;
        }
        __syncthreads();
    }
#pragma unroll
    for (int i = 0; i < 4; i++)
#pragma unroll
        for (int j = 0; j < 3; j++)
            g_lqkv_part[kq][(size_t)(m0 + rg * 4 + i) * 48 + cg * 3 + j] = acc[i][j];
}

__global__ __launch_bounds__(256)
void lora_down_o(const float* __restrict__ woA)
{
    __shared__ float xs[32][68];
    __shared__ float ws[32][16];
    const int tid = threadIdx.x;
    const int m0  = blockIdx.x * 64;
    const int kq  = blockIdx.y;
    const int cg  = tid & 15;
    const int rg  = tid >> 4;
    const int KSEG = DD / LKS;

    float acc[4] = {0.f, 0.f, 0.f, 0.f};
    const int srow = tid >> 2, seg = tid & 3;
    for (int k0 = kq * KSEG; k0 < kq * KSEG + KSEG; k0 += 32) {
        const float* xp = &g_attn[(size_t)(m0 + srow) * DD + k0 + seg * 8];
        float4 v0 = *(const float4*)xp;
        float4 v1 = *(const float4*)(xp + 4);
        const int sbk = seg * 8;
        xs[sbk + 0][srow] = v0.x; xs[sbk + 1][srow] = v0.y;
        xs[sbk + 2][srow] = v0.z; xs[sbk + 3][srow] = v0.w;
        xs[sbk + 4][srow] = v1.x; xs[sbk + 5][srow] = v1.y;
        xs[sbk + 6][srow] = v1.z; xs[sbk + 7][srow] = v1.w;
        for (int idx = tid; idx < 32 * 16; idx += 256) {
            int kk = idx >> 4, c = idx & 15;
            ws[kk][c] = woA[(size_t)(k0 + kk) * 16 + c];
        }
        __syncthreads();
#pragma unroll
        for (int kk = 0; kk < 32; kk++) {
            float4 xv = *(const float4*)&xs[kk][rg * 4];
            float w0 = ws[kk][cg];
            acc[0] += xv.x * w0; acc[1] += xv.y * w0;
            acc[2] += xv.z * w0; acc[3] += xv.w * w0;
        }
        __syncthreads();
    }
#pragma unroll
    for (int i = 0; i < 4; i++)
        g_lo_part[kq][(size_t)(m0 + rg * 4 + i) * 16 + cg] = acc[i];
}

// ---------------------------------------------------------------------------
// scatter prev_key/prev_value into bf16 hi/lo attention layouts
// ---------------------------------------------------------------------------
__global__ void scatter_prev(const float* __restrict__ pk, const float* __restrict__ pv)
{
    int idx = blockIdx.x * blockDim.x + threadIdx.x;   // over B*P*H*(DH/4)
    if (idx >= BB * PP * HH * (DH / 4)) return;
    int d4 = idx & 31;
    int h  = (idx >> 5) & 15;
    int p  = (idx >> 9) & 1023;
    int b  = idx >> 19;

    size_t base = (((size_t)(b * HH + h) * PSL) + p) * DH + d4 * 4;
    float4 kq = *(const float4*)&pk[(size_t)idx * 4];
    float4 vv = *(const float4*)&pv[(size_t)idx * 4];
    bsplit4_store(kq, g_Kh + base, g_Kl + base, 0);
    bsplit4_store(vv, g_Vh + base, g_Vl + base, 0);
}

// ---------------------------------------------------------------------------
// HMMA GEMM: 128x128 CTA tile, bf16-split (3 virtual K passes), cp.async,
// depth-3 pipeline (fetch issued 2 iterations ahead), one barrier/stage,
// 2 CTAs/SM.
//   mode 0: q (LoRA+RoPE+scale -> Qh/Ql)   mode 1: k (LoRA+RoPE -> Kh/Kl)
//   mode 2: v (LoRA -> Vh/Vl)              mode 3: o (LoRA -> Cout fp32)
// smem: A bufs [3][16384] at 0 | B bufs [3][16384] at 49152 | wBs at 98304
// ---------------------------------------------------------------------------
#define GEMM_SMEM (98304 + 8192 + 128)
#define NSTAGE 96

__global__ __launch_bounds__(256, 2)
void gemm_tc(const float* __restrict__ psc,
             const float* __restrict__ fcos, const float* __restrict__ fsin,
             const float* __restrict__ Bq, const float* __restrict__ Bk,
             const float* __restrict__ Bv,
             float* __restrict__ Cout, int is_o)
{
    extern __shared__ __align__(128) char dsm[];
    const uint32_t smem_raw = smem_to_u32(dsm);
    const uint32_t sb = (smem_raw + 127) & ~127u;
    char* sgen = dsm + (sb - smem_raw);

    const int tid  = threadIdx.x;
    const int lane = tid & 31;
    const int w    = tid >> 5;
    const int mode = is_o ? 3 : blockIdx.z;
    const int m0   = blockIdx.y * 128;
    const int n0   = blockIdx.x * 128;

    const __nv_bfloat16* __restrict__ Ahi = is_o ? g_ahi : g_xhi;
    const __nv_bfloat16* __restrict__ Alo = is_o ? g_alo : g_xlo;
    const __nv_bfloat16* __restrict__ Bhi = g_whi + (size_t)mode * DD * DD;
    const __nv_bfloat16* __restrict__ Blo = g_wlo + (size_t)mode * DD * DD;

    // LoRA wB tile -> smem (region disjoint from mainloop tiles)
    float* wBs = (float*)(sgen + 98304);
    const float* wBp = (mode == 0 || mode == 3) ? Bq : ((mode == 1) ? Bk : Bv);
    for (int idx = tid; idx < 16 * 128; idx += 256)
        wBs[idx] = wBp[(idx >> 7) * DD + n0 + (idx & 127)];

    const int rb = tid >> 3;
    const int c8 = tid & 7;
    const uint32_t dx   = (uint32_t)((c8 ^ (rb & 7)) * 16);
    const uint32_t drow = (uint32_t)(rb * 128);

    const int wm = (w & 1) * 64;
    const int wn = (w >> 1) * 32;
    const int lrow = lane & 15;
    const uint32_t lcol = (uint32_t)((lane >> 4) * 16);
    uint32_t arow[4], amask[4], brow[2], bmask[2];
#pragma unroll
    for (int i = 0; i < 4; i++) {
        int rr = wm + i * 16 + lrow;
        arow[i] = (uint32_t)(rr * 128); amask[i] = (uint32_t)((rr & 7) * 16);
    }
#pragma unroll
    for (int jj = 0; jj < 2; jj++) {
        int rr = wn + jj * 16 + lrow;
        brow[jj] = (uint32_t)(rr * 128); bmask[jj] = (uint32_t)((rr & 7) * 16);
    }

    float d[4][4][4];
#pragma unroll
    for (int i = 0; i < 4; i++)
#pragma unroll
        for (int j = 0; j < 4; j++)
#pragma unroll
            for (int q = 0; q < 4; q++) d[i][j][q] = 0.f;

    auto issue = [&](int s, int buf) {
        const int ko  = (s & 31) << 6;
        const __nv_bfloat16* As = (s >= 64) ? Alo : Ahi;
        const __nv_bfloat16* Bs = (s >= 32 && s < 64) ? Blo : Bhi;
        const __nv_bfloat16* ap = As + (size_t)(m0 + rb) * DD + ko + c8 * 8;
        const __nv_bfloat16* bp = Bs + (size_t)(n0 + rb) * DD + ko + c8 * 8;
        const uint32_t da = sb + (uint32_t)(buf * 16384) + drow + dx;
        const uint32_t db = sb + 49152u + (uint32_t)(buf * 16384) + drow + dx;
#pragma unroll
        for (int t = 0; t < 4; t++) {
            cp16(da + t * 32 * 128, ap + (size_t)t * 32 * DD);
            cp16(db + t * 32 * 128, bp + (size_t)t * 32 * DD);
        }
        CP_COMMIT();
    };

    issue(0, 0);
    issue(1, 1);
    int buf_cur = 0, buf_pre = 2;      // buffer for stage s, and for stage s+2
    for (int s = 0; s < NSTAGE; s++) {
        if (s + 1 < NSTAGE) CP_WAIT1();   // stage s landed (s+1 may be in flight)
        else                CP_WAIT0();
        __syncthreads();                  // visibility + all warps done with buf_pre
        if (s + 2 < NSTAGE) issue(s + 2, buf_pre);

        const uint32_t abase = sb + (uint32_t)(buf_cur * 16384);
        const uint32_t bbase = sb + 49152u + (uint32_t)(buf_cur * 16384);
#pragma unroll
        for (int kk = 0; kk < 4; kk++) {
            const uint32_t kb = (uint32_t)(kk * 32);
            uint32_t bf[4][2];
#pragma unroll
            for (int jj = 0; jj < 2; jj++) {
                uint32_t t4[4];
                ldsm4(t4, bbase + brow[jj] + ((kb + lcol) ^ bmask[jj]));
                bf[jj * 2][0]     = t4[0];
                bf[jj * 2 + 1][0] = t4[1];
                bf[jj * 2][1]     = t4[2];
                bf[jj * 2 + 1][1] = t4[3];
            }
            uint32_t af[4][4];
#pragma unroll
            for (int i = 0; i < 4; i++)
                ldsm4(af[i], abase + arow[i] + ((kb + lcol) ^ amask[i]));
#pragma unroll
            for (int i = 0; i < 4; i++)
#pragma unroll
                for (int j = 0; j < 4; j++)
                    mma16816(d[i][j], af[i], bf[j]);
        }
        buf_cur = buf_cur + 1; if (buf_cur == 3) buf_cur = 0;
        buf_pre = buf_pre + 1; if (buf_pre == 3) buf_pre = 0;
    }
    __syncthreads();   // all compute done before Cst aliases the buffers

    // --- stage C into smem (stride 132) ---
    float* Cst = (float*)sgen;
    {
        const int qr = lane >> 2;
        const int qc = (lane & 3) * 2;
#pragma unroll
        for (int i = 0; i < 4; i++) {
#pragma unroll
            for (int j = 0; j < 4; j++) {
                int r0 = wm + i * 16 + qr;
                int cc = wn + j * 8 + qc;
                *(float2*)&Cst[r0 * 132 + cc]       = make_float2(d[i][j][0], d[i][j][1]);
                *(float2*)&Cst[(r0 + 8) * 132 + cc] = make_float2(d[i][j][2], d[i][j][3]);
            }
        }
    }
    __syncthreads();

    // --- per-row epilogue ---
    {
        const int row = tid >> 1;
        const int ch  = (tid & 1) * 64;
        const int m   = m0 + row;
        const int b   = m >> 11, sq = m & 2047;
        const float ps = psc[b];
        float aLv[16];
#pragma unroll
        for (int r = 0; r < 16; r++) {
            float sum = 0.f;
            if (is_o) {
                size_t o = (size_t)m * 16 + r;
#pragma unroll
                for (int p = 0; p < LKS; p++) sum += g_lo_part[p][o];
            } else {
                size_t o = (size_t)m * 48 + mode * 16 + r;
#pragma unroll
                for (int p = 0; p < LKS; p++) sum += g_lqkv_part[p][o];
            }
            aLv[r] = sum * ps;
        }

        const int h = n0 >> 7;
        // 1/sqrt(128) * log2(e): softmax runs in exp2 domain
        const float scl = 0.12751743645506170f;
#pragma unroll
        for (int half = 0; half < 2; half++) {
            const int cb = ch + half * 32;
            float c[32];
#pragma unroll
            for (int j = 0; j < 32; j++) {
                float lora = 0.f;
#pragma unroll
                for (int r = 0; r < 16; r++) lora += aLv[r] * wBs[r * 128 + cb + j];
                c[j] = Cst[row * 132 + cb + j] + lora;
            }
            if (mode == 3) {
                float* dst = &Cout[(size_t)m * DD + n0 + cb];
#pragma unroll
                for (int j = 0; j < 32; j += 4)
                    *(float4*)(dst + j) = make_float4(c[j], c[j+1], c[j+2], c[j+3]);
            } else if (mode == 2) {
                size_t off = (((size_t)(b * HH + h) * PSL) + PP + sq) * DH + cb;
                store32_split(c, g_Vh + off, g_Vl + off);
            } else {
                float v[32];
#pragma unroll
                for (int p = 0; p < 16; p++) {
                    int dcol = cb + 2 * p;
                    float cz = fcos[sq * 64 + (dcol >> 1)];
                    float sz = fsin[sq * 64 + (dcol >> 1)];
                    float a = c[2 * p], bq = c[2 * p + 1];
                    v[2 * p]     = a * cz - bq * sz;
                    v[2 * p + 1] = a * sz + bq * cz;
                }
                if (mode == 0) {
#pragma unroll
                    for (int j = 0; j < 32; j++) v[j] *= scl;
                    size_t off = (((size_t)(b * HH + h) * SS) + sq) * DH + cb;
                    store32_split(v, g_Qh + off, g_Ql + off);
                } else {
                    size_t off = (((size_t)(b * HH + h) * PSL) + PP + sq) * DH + cb;
                    store32_split(v, g_Kh + off, g_Kl + off);
                }
            }
        }
    }
}

// ---------------------------------------------------------------------------
// HMMA flash attention: 128-q CTA, 8 warps (16 q each), 64-key tiles,
// bf16 hi/lo split on Q/K and P/V, softmax in exp2 domain, one barrier/tile.
// smem: QH 0 | QL 32768 | stage s at 65536+s*65536: KH,KL,VH,VL (16KB each)
// ---------------------------------------------------------------------------
#define ATTN_SMEM (65536 + 2 * 65536)

__global__ __launch_bounds__(256, 1)
void attn_mma()
{
    extern __shared__ __align__(128) char smdyn[];
    const uint32_t sb = smem_to_u32(smdyn);

    const int tid  = threadIdx.x;
    const int lane = tid & 31;
    const int w    = tid >> 5;
    const int bh   = blockIdx.y;
    const int i0   = blockIdx.x * 128;

    const __nv_bfloat16* Qhp = g_Qh + ((size_t)bh * SS + i0) * DH;
    const __nv_bfloat16* Qlp = g_Ql + ((size_t)bh * SS + i0) * DH;
    const __nv_bfloat16* Khp = g_Kh + (size_t)bh * PSL * DH;
    const __nv_bfloat16* Klp = g_Kl + (size_t)bh * PSL * DH;
    const __nv_bfloat16* Vhp = g_Vh + (size_t)bh * PSL * DH;
    const __nv_bfloat16* Vlp = g_Vl + (size_t)bh * PSL * DH;

    // ---- Q tiles (hi+lo), one cp.async group ----
    {
        int row = tid >> 1, cg = tid & 1;
        const __nv_bfloat16* qh = Qhp + (size_t)row * DH;
        const __nv_bfloat16* ql = Qlp + (size_t)row * DH;
        uint32_t dst = sb + row * 256;
#pragma unroll
        for (int i = 0; i < 8; i++) {
            int c = cg * 8 + i;
            uint32_t so = (uint32_t)((c ^ (row & 7)) * 16);
            cp16(dst + so, qh + c * 8);
            cp16(dst + 32768 + so, ql + c * 8);
        }
    }
    CP_COMMIT();

    const int ntiles = 18 + (i0 >> 6);
    auto issue_kv = [&](int t) {
        int row = tid >> 2, cg = tid & 3, j0 = t * 64;
        size_t goff = (size_t)(j0 + row) * DH;
        uint32_t dst = sb + 65536u + (uint32_t)((t & 1) * 65536) + row * 256;
#pragma unroll
        for (int i = 0; i < 4; i++) {
            int c = cg * 4 + i;
            uint32_t so = (uint32_t)((c ^ (row & 7)) * 16);
            cp16(dst + so,          Khp + goff + c * 8);
            cp16(dst + 16384 + so,  Klp + goff + c * 8);
            cp16(dst + 32768 + so,  Vhp + goff + c * 8);
            cp16(dst + 49152 + so,  Vlp + goff + c * 8);
        }
        CP_COMMIT();
    };
    issue_kv(0);

    float o[16][4];
#pragma unroll
    for (int i = 0; i < 16; i++)
#pragma unroll
        for (int q = 0; q < 4; q++) o[i][q] = 0.f;
    float m0r = -1e30f, m1r = -1e30f, l0 = 0.f, l1 = 0.f;

    const int lrow = lane & 15;
    const int lh   = lane >> 4;
    const uint32_t qaddr = sb + (uint32_t)((w * 16 + lrow) * 256);
    const int qsw = (w * 16 + lrow) & 7;
    const int ksw = lrow & 7;
    const int lim0 = PP + i0 + w * 16 + (lane >> 2);

    for (int t = 0; t < ntiles; t++) {
        CP_WAIT0();            // tile t (and Q on t=0) landed
        __syncthreads();       // visibility + all warps done with buffer (t+1)&1
        if (t + 1 < ntiles) issue_kv(t + 1);

        const uint32_t KHb = sb + 65536u + (uint32_t)((t & 1) * 65536);

        // ---- S = Q K^T (3 split passes fused) ----
        float s[8][4];
#pragma unroll
        for (int na = 0; na < 8; na++)
#pragma unroll
            for (int q = 0; q < 4; q++) s[na][q] = 0.f;

#pragma unroll
        for (int kk = 0; kk < 8; kk++) {
            uint32_t afh[4], afl[4];
            uint32_t ca = (uint32_t)(((kk * 2 + lh) ^ qsw) * 16);
            ldsm4(afh, qaddr + ca);
            ldsm4(afl, qaddr + 32768 + ca);
            uint32_t ck = (uint32_t)(((kk * 2 + lh) ^ ksw) * 16);
#pragma unroll
            for (int nb = 0; nb < 4; nb++) {
                uint32_t raddr = KHb + (uint32_t)((nb * 16 + lrow) * 256) + ck;
                uint32_t tkh[4], tkl[4];
                ldsm4(tkh, raddr);
                ldsm4(tkl, raddr + 16384);
                uint32_t b0h[2] = {tkh[0], tkh[2]}, b1h[2] = {tkh[1], tkh[3]};
                uint32_t b0l[2] = {tkl[0], tkl[2]}, b1l[2] = {tkl[1], tkl[3]};
                mma16816(s[2 * nb],     afh, b0h);
                mma16816(s[2 * nb],     afh, b0l);
                mma16816(s[2 * nb],     afl, b0h);
                mma16816(s[2 * nb + 1], afh, b1h);
                mma16816(s[2 * nb + 1], afh, b1l);
                mma16816(s[2 * nb + 1], afl, b1h);
            }
        }

        // ---- mask (last two tiles only) ----
        const int j0 = t * 64;
        if (j0 + 63 > PP + i0) {
#pragma unroll
            for (int na = 0; na < 8; na++) {
                int j = j0 + na * 8 + (lane & 3) * 2;
                if (j > lim0)         s[na][0] = -1e30f;
                if (j + 1 > lim0)     s[na][1] = -1e30f;
                if (j > lim0 + 8)     s[na][2] = -1e30f;
                if (j + 1 > lim0 + 8) s[na][3] = -1e30f;
            }
        }

        // ---- online softmax in exp2 domain (log2e folded into Q scale) ----
        float mt0 = -1e30f, mt1 = -1e30f;
#pragma unroll
        for (int na = 0; na < 8; na++) {
            mt0 = fmaxf(mt0, fmaxf(s[na][0], s[na][1]));
            mt1 = fmaxf(mt1, fmaxf(s[na][2], s[na][3]));
        }
        mt0 = fmaxf(mt0, __shfl_xor_sync(0xffffffffu, mt0, 1));
        mt0 = fmaxf(mt0, __shfl_xor_sync(0xffffffffu, mt0, 2));
        mt1 = fmaxf(mt1, __shfl_xor_sync(0xffffffffu, mt1, 1));
        mt1 = fmaxf(mt1, __shfl_xor_sync(0xffffffffu, mt1, 2));
        float mn0 = fmaxf(m0r, mt0), mn1 = fmaxf(m1r, mt1);
        float a0 = ex2f(m0r - mn0), a1 = ex2f(m1r - mn1);
        m0r = mn0; m1r = mn1;
        float s0 = 0.f, s1 = 0.f;
#pragma unroll
        for (int na = 0; na < 8; na++) {
            s[na][0] = ex2f(s[na][0] - mn0); s0 += s[na][0];
            s[na][1] = ex2f(s[na][1] - mn0); s0 += s[na][1];
            s[na][2] = ex2f(s[na][2] - mn1); s1 += s[na][2];
            s[na][3] = ex2f(s[na][3] - mn1); s1 += s[na][3];
        }
        s0 += __shfl_xor_sync(0xffffffffu, s0, 1);
        s0 += __shfl_xor_sync(0xffffffffu, s0, 2);
        s1 += __shfl_xor_sync(0xffffffffu, s1, 1);
        s1 += __shfl_xor_sync(0xffffffffu, s1, 2);
        l0 = l0 * a0 + s0;
        l1 = l1 * a1 + s1;
#pragma unroll
        for (int na = 0; na < 16; na++) {
            o[na][0] *= a0; o[na][1] *= a0;
            o[na][2] *= a1; o[na][3] *= a1;
        }

        // ---- O += P V (P from registers, 3 split passes) ----
        const uint32_t VHb = KHb + 32768u;
#pragma unroll
        for (int jj = 0; jj < 4; jj++) {
            uint32_t ph[4], pl[4];
            bfsplit2(s[2 * jj][0],     s[2 * jj][1],     ph[0], pl[0]);
            bfsplit2(s[2 * jj][2],     s[2 * jj][3],     ph[1], pl[1]);
            bfsplit2(s[2 * jj + 1][0], s[2 * jj + 1][1], ph[2], pl[2]);
            bfsplit2(s[2 * jj + 1][2], s[2 * jj + 1][3], ph[3], pl[3]);
#pragma unroll
            for (int db = 0; db < 8; db++) {
                uint32_t vaddr = VHb + (uint32_t)((jj * 16 + lrow) * 256)
                               + (uint32_t)(((db * 2 + lh) ^ ksw) * 16);
                uint32_t tvh[4], tvl[4];
                ldsm4t(tvh, vaddr);
                ldsm4t(tvl, vaddr + 16384);
                uint32_t bh0[2] = {tvh[0], tvh[1]}, bh1[2] = {tvh[2], tvh[3]};
                uint32_t bl0[2] = {tvl[0], tvl[1]}, bl1[2] = {tvl[2], tvl[3]};
                mma16816(o[2 * db],     ph, bh0);
                mma16816(o[2 * db],     pl, bh0);
                mma16816(o[2 * db],     ph, bl0);
                mma16816(o[2 * db + 1], ph, bh1);
                mma16816(o[2 * db + 1], pl, bh1);
                mma16816(o[2 * db + 1], ph, bl1);
            }
        }
    }

    // ---- normalize + write (fp32 g_attn and bf16 hi/lo for O gemm) ----
    {
        float inv0 = 1.0f / l0, inv1 = 1.0f / l1;
        int q0 = i0 + w * 16 + (lane >> 2);
        int b = bh >> 4, h = bh & 15;
        size_t base0 = ((size_t)b * SS + q0) * DD + h * DH + (lane & 3) * 2;
        size_t base1 = base0 + (size_t)8 * DD;
#pragma unroll
        for (int na = 0; na < 16; na++) {
            size_t o0 = base0 + na * 8;
            size_t o1 = base1 + na * 8;
            float f0 = o[na][0] * inv0, f1 = o[na][1] * inv0;
            float f2 = o[na][2] * inv1, f3 = o[na][3] * inv1;
            *(float2*)&g_attn[o0] = make_float2(f0, f1);
            *(float2*)&g_attn[o1] = make_float2(f2, f3);
            uint32_t h2, l2;
            bfsplit2(f0, f1, h2, l2);
            *(uint32_t*)&g_ahi[o0] = h2;
            *(uint32_t*)&g_alo[o0] = l2;
            bfsplit2(f2, f3, h2, l2);
            *(uint32_t*)&g_ahi[o1] = h2;
            *(uint32_t*)&g_alo[o1] = l2;
        }
    }
}

// ---------------------------------------------------------------------------
// Launch
// ---------------------------------------------------------------------------
extern "C" void kernel_launch(void* const* d_in, const int* in_sizes, int n_in,
                              void* d_out, int out_size)
{
    const float* x    = (const float*)d_in[0];
    const float* fcos = (const float*)d_in[1];
    const float* fsin = (const float*)d_in[2];
    // d_in[3] = mask (unused; causality computed analytically)
    const float* pk   = (const float*)d_in[4];
    const float* pv   = (const float*)d_in[5];
    const float* ps   = (const float*)d_in[6];
    const float* wq   = (const float*)d_in[7];
    const float* wk   = (const float*)d_in[8];
    const float* wv   = (const float*)d_in[9];
    const float* wo   = (const float*)d_in[10];
    const float* wqA  = (const float*)d_in[11];
    const float* wqB  = (const float*)d_in[12];
    const float* wkA  = (const float*)d_in[13];
    const float* wkB  = (const float*)d_in[14];
    const float* wvA  = (const float*)d_in[15];
    const float* wvB  = (const float*)d_in[16];
    const float* woA  = (const float*)d_in[17];
    const float* woB  = (const float*)d_in[18];
    float* out        = (float*)d_out;

    static void* sym_xhi = nullptr, *sym_xlo = nullptr;
    if (!sym_xhi) {
        cudaGetSymbolAddress(&sym_xhi, g_xhi);
        cudaGetSymbolAddress(&sym_xlo, g_xlo);
    }

    cudaFuncSetAttribute(gemm_tc, cudaFuncAttributeMaxDynamicSharedMemorySize,
                         GEMM_SMEM);
    cudaFuncSetAttribute(attn_mma, cudaFuncAttributeMaxDynamicSharedMemorySize,
                         ATTN_SMEM);

    scatter_prev<<<(BB * PP * HH * (DH / 4) + 255) / 256, 256>>>(pk, pv);
    split4<<<(MM * DD / 4) / 256, 256>>>(x, (__nv_bfloat16*)sym_xhi,
                                         (__nv_bfloat16*)sym_xlo);
    split_w4<<<dim3((DD * DD / 4) / 256, 1, 4), 256>>>(wq, wk, wv, wo);
    lora_down_qkv<<<dim3(MM / 64, LKS), 256>>>(x, wqA, wkA, wvA);

    gemm_tc<<<dim3(DD / 128, MM / 128, 3), 256, GEMM_SMEM>>>(
        ps, fcos, fsin, wqB, wkB, wvB, nullptr, 0);

    attn_mma<<<dim3(SS / 128, BB * HH), 256, ATTN_SMEM>>>();

    lora_down_o<<<dim3(MM / 64, LKS), 256>>>(woA);

    gemm_tc<<<dim3(DD / 128, MM / 128, 1), 256, GEMM_SMEM>>>(
        ps, fcos, fsin, woB, nullptr, nullptr, out, 1);
}

// round 12
// speedup vs baseline: 1.0206x; 1.0206x over previous
#include <cuda_runtime.h>
#include <cuda_bf16.h>
#include <cstdint>

typedef unsigned long long ull;

// Problem constants
#define BB   2
#define SS   2048
#define PP   1024
#define DD   2048
#define HH   16
#define DH   128
#define PSL  3072          // P + S
#define MM   4096          // B * S
#define LKS  8             // lora split-K factor

// ---------------------------------------------------------------------------
// Scratch (device globals; no allocation allowed in kernel_launch)
// ---------------------------------------------------------------------------
__device__ float g_attn[(size_t)MM * DD];             // [m, h*DH+d] fp32
__device__ float g_lqkv_part[LKS][(size_t)MM * 48];   // lora down partials (q|k|v)
__device__ float g_lo_part[LKS][(size_t)MM * 16];

// bf16 split operands
__device__ __nv_bfloat16 g_xhi[(size_t)MM * DD];
__device__ __nv_bfloat16 g_xlo[(size_t)MM * DD];
__device__ __nv_bfloat16 g_ahi[(size_t)MM * DD];
__device__ __nv_bfloat16 g_alo[(size_t)MM * DD];
__device__ __nv_bfloat16 g_whi[(size_t)4 * DD * DD];  // wq|wk|wv|wo
__device__ __nv_bfloat16 g_wlo[(size_t)4 * DD * DD];

// attention operands, bf16 hi/lo split
__device__ __nv_bfloat16 g_Qh[(size_t)BB * HH * SS * DH];   // [b,h,s,d] (pre-scaled)
__device__ __nv_bfloat16 g_Ql[(size_t)BB * HH * SS * DH];
__device__ __nv_bfloat16 g_Kh[(size_t)BB * HH * PSL * DH];  // [b,h,j,d]
__device__ __nv_bfloat16 g_Kl[(size_t)BB * HH * PSL * DH];
__device__ __nv_bfloat16 g_Vh[(size_t)BB * HH * PSL * DH];  // [b,h,j,d]
__device__ __nv_bfloat16 g_Vl[(size_t)BB * HH * PSL * DH];

// ---------------------------------------------------------------------------
// helpers
// ---------------------------------------------------------------------------
__device__ __forceinline__ uint32_t smem_to_u32(const void* smem_ptr) {
    uint32_t addr;
    asm("{ .reg .u64 tmp; cvta.to.shared.u64 tmp, %1; cvt.u32.u64 %0, tmp; }"
        : "=r"(addr) : "l"(smem_ptr));
    return addr;
}
__device__ __forceinline__ void cp16(uint32_t dst, const void* src) {
    asm volatile("cp.async.cg.shared.global [%0], [%1], 16;"
                 :: "r"(dst), "l"(src) : "memory");
}
#define CP_COMMIT() asm volatile("cp.async.commit_group;" ::: "memory")
#define CP_WAIT1()  asm volatile("cp.async.wait_group 1;" ::: "memory")
#define CP_WAIT0()  asm volatile("cp.async.wait_group 0;" ::: "memory")

__device__ __forceinline__ void ldsm4(uint32_t a[4], uint32_t addr) {
    asm volatile("ldmatrix.sync.aligned.m8n8.x4.shared.b16 {%0,%1,%2,%3}, [%4];"
        : "=r"(a[0]), "=r"(a[1]), "=r"(a[2]), "=r"(a[3]) : "r"(addr));
}
__device__ __forceinline__ void ldsm4t(uint32_t a[4], uint32_t addr) {
    asm volatile("ldmatrix.sync.aligned.m8n8.x4.trans.shared.b16 {%0,%1,%2,%3}, [%4];"
        : "=r"(a[0]), "=r"(a[1]), "=r"(a[2]), "=r"(a[3]) : "r"(addr));
}
__device__ __forceinline__ void mma16816(float d[4], const uint32_t a[4],
                                         const uint32_t b[2]) {
    asm volatile(
        "mma.sync.aligned.m16n8k16.row.col.f32.bf16.bf16.f32 "
        "{%0,%1,%2,%3}, {%4,%5,%6,%7}, {%8,%9}, {%0,%1,%2,%3};"
        : "+f"(d[0]), "+f"(d[1]), "+f"(d[2]), "+f"(d[3])
        : "r"(a[0]), "r"(a[1]), "r"(a[2]), "r"(a[3]), "r"(b[0]), "r"(b[1]));
}
__device__ __forceinline__ float ex2f(float x) {
    float r; asm("ex2.approx.ftz.f32 %0, %1;" : "=f"(r) : "f"(x)); return r;
}

// Truncation-based split of two floats into packed bf16x2 hi (exact truncation)
// and lo (RN of residual). hi keeps a in low half, b in high half.
__device__ __forceinline__ void bfsplit2(float a, float b, uint32_t& h, uint32_t& l) {
    uint32_t ai = __float_as_uint(a), bi = __float_as_uint(b);
    h = __byte_perm(ai, bi, 0x7632);
    float ra = a - __uint_as_float(ai & 0xffff0000u);
    float rb = b - __uint_as_float(bi & 0xffff0000u);
    asm("cvt.rn.bf16x2.f32 %0, %1, %2;" : "=r"(l) : "f"(rb), "f"(ra));
}
// split-store 32 consecutive floats as bf16 hi/lo (dst 8B-aligned)
__device__ __forceinline__ void store32_split(const float* v,
                                              __nv_bfloat16* dh, __nv_bfloat16* dl) {
    uint32_t hs[16], ls[16];
#pragma unroll
    for (int j = 0; j < 16; j++) bfsplit2(v[2 * j], v[2 * j + 1], hs[j], ls[j]);
#pragma unroll
    for (int j = 0; j < 4; j++) {
        ((uint4*)dh)[j] = *(uint4*)&hs[j * 4];
        ((uint4*)dl)[j] = *(uint4*)&ls[j * 4];
    }
}

// ---------------------------------------------------------------------------
// fp32 -> bf16 hi/lo split kernels (x and weights)
// ---------------------------------------------------------------------------
__device__ __forceinline__ void bsplit4_store(float4 v, __nv_bfloat16* hi,
                                              __nv_bfloat16* lo, size_t i4)
{
    uint32_t h0, l0, h1, l1;
    bfsplit2(v.x, v.y, h0, l0);
    bfsplit2(v.z, v.w, h1, l1);
    ((uint2*)hi)[i4] = make_uint2(h0, h1);
    ((uint2*)lo)[i4] = make_uint2(l0, l1);
}

__global__ __launch_bounds__(256)
void split4(const float* __restrict__ src, __nv_bfloat16* __restrict__ hi,
            __nv_bfloat16* __restrict__ lo)
{
    size_t i = (size_t)blockIdx.x * 256 + threadIdx.x;
    float4 v = ((const float4*)src)[i];
    bsplit4_store(v, hi, lo, i);
}

__global__ __launch_bounds__(256)
void split_w4(const float* __restrict__ w0, const float* __restrict__ w1,
              const float* __restrict__ w2, const float* __restrict__ w3)
{
    const int z = blockIdx.z;
    const float* src = (z == 0) ? w0 : ((z == 1) ? w1 : ((z == 2) ? w2 : w3));
    __nv_bfloat16* hi = g_whi + (size_t)z * DD * DD;
    __nv_bfloat16* lo = g_wlo + (size_t)z * DD * DD;
    size_t i = (size_t)blockIdx.x * 256 + threadIdx.x;
    float4 v = ((const float4*)src)[i];
    bsplit4_store(v, hi, lo, i);
}

// ---------------------------------------------------------------------------
// LoRA down-projections: split-K=LKS, thread = 4 rows x 3 cols (qkv) / 4x1 (o)
// ---------------------------------------------------------------------------
__global__ __launch_bounds__(256)
void lora_down_qkv(const float* __restrict__ x,
                   const float* __restrict__ wqA,
                   const float* __restrict__ wkA,
                   const float* __restrict__ wvA)
{
    __shared__ float xs[32][68];
    __shared__ float ws[32][48];
    const int tid = threadIdx.x;
    const int m0  = blockIdx.x * 64;
    const int kq  = blockIdx.y;
    const int cg  = tid & 15;
    const int rg  = tid >> 4;
    const int KSEG = DD / LKS;            // 256

    float acc[4][3];
#pragma unroll
    for (int i = 0; i < 4; i++)
#pragma unroll
        for (int j = 0; j < 3; j++) acc[i][j] = 0.f;

    const int srow = tid >> 2, seg = tid & 3;
    for (int k0 = kq * KSEG; k0 < kq * KSEG + KSEG; k0 += 32) {
        const float* xp = &x[(size_t)(m0 + srow) * DD + k0 + seg * 8];
        float4 v0 = *(const float4*)xp;
        float4 v1 = *(const float4*)(xp + 4);
        const int sbk = seg * 8;
        xs[sbk + 0][srow] = v0.x; xs[sbk + 1][srow] = v0.y;
        xs[sbk + 2][srow] = v0.z; xs[sbk + 3][srow] = v0.w;
        xs[sbk + 4][srow] = v1.x; xs[sbk + 5][srow] = v1.y;
        xs[sbk + 6][srow] = v1.z; xs[sbk + 7][srow] = v1.w;
        for (int idx = tid; idx < 32 * 48; idx += 256) {
            int kk = idx / 48, c = idx % 48;
            const float* w = (c < 16) ? wqA : ((c < 32) ? wkA : wvA);
            ws[kk][c] = w[(size_t)(k0 + kk) * 16 + (c & 15)];
        }
        __syncthreads();
#pragma unroll
        for (int kk = 0; kk < 32; kk++) {
            float4 xv = *(const float4*)&xs[kk][rg * 4];
            float w0 = ws[kk][cg * 3 + 0];
            float w1 = ws[kk][cg * 3 + 1];
            float w2 = ws[kk][cg * 3 + 2];
            acc[0][0] += xv.x * w0; acc[0][1] += xv.x * w1; acc[0][2] += xv.x * w2;
            acc[1][0] += xv.y * w0; acc[1][1] += xv.y * w1; acc[1][2] += xv.y * w2;
            acc[2][0] += xv.z * w0; acc[2][1] += xv.z * w1; acc[2][2] += xv.z * w2;
            acc[3][0] += xv.w * w0; acc[3][1] += xv.w * w1; acc[3][2] += xv.w * w2;
        }
        __syncthreads();
    }
#pragma unroll
    for (int i = 0; i < 4; i++)
#pragma unroll
        for (int j = 0; j < 3; j++)
            g_lqkv_part[kq][(size_t)(m0 + rg * 4 + i) * 48 + cg * 3 + j] = acc[i][j];
}

__global__ __launch_bounds__(256)
void lora_down_o(const float* __restrict__ woA)
{
    __shared__ float xs[32][68];
    __shared__ float ws[32][16];
    const int tid = threadIdx.x;
    const int m0  = blockIdx.x * 64;
    const int kq  = blockIdx.y;
    const int cg  = tid & 15;
    const int rg  = tid >> 4;
    const int KSEG = DD / LKS;

    float acc[4] = {0.f, 0.f, 0.f, 0.f};
    const int srow = tid >> 2, seg = tid & 3;
    for (int k0 = kq * KSEG; k0 < kq * KSEG + KSEG; k0 += 32) {
        const float* xp = &g_attn[(size_t)(m0 + srow) * DD + k0 + seg * 8];
        float4 v0 = *(const float4*)xp;
        float4 v1 = *(const float4*)(xp + 4);
        const int sbk = seg * 8;
        xs[sbk + 0][srow] = v0.x; xs[sbk + 1][srow] = v0.y;
        xs[sbk + 2][srow] = v0.z; xs[sbk + 3][srow] = v0.w;
        xs[sbk + 4][srow] = v1.x; xs[sbk + 5][srow] = v1.y;
        xs[sbk + 6][srow] = v1.z; xs[sbk + 7][srow] = v1.w;
        for (int idx = tid; idx < 32 * 16; idx += 256) {
            int kk = idx >> 4, c = idx & 15;
            ws[kk][c] = woA[(size_t)(k0 + kk) * 16 + c];
        }
        __syncthreads();
#pragma unroll
        for (int kk = 0; kk < 32; kk++) {
            float4 xv = *(const float4*)&xs[kk][rg * 4];
            float w0 = ws[kk][cg];
            acc[0] += xv.x * w0; acc[1] += xv.y * w0;
            acc[2] += xv.z * w0; acc[3] += xv.w * w0;
        }
        __syncthreads();
    }
#pragma unroll
    for (int i = 0; i < 4; i++)
        g_lo_part[kq][(size_t)(m0 + rg * 4 + i) * 16 + cg] = acc[i];
}

// ---------------------------------------------------------------------------
// scatter prev_key/prev_value into bf16 hi/lo attention layouts
// ---------------------------------------------------------------------------
__global__ void scatter_prev(const float* __restrict__ pk, const float* __restrict__ pv)
{
    int idx = blockIdx.x * blockDim.x + threadIdx.x;   // over B*P*H*(DH/4)
    if (idx >= BB * PP * HH * (DH / 4)) return;
    int d4 = idx & 31;
    int h  = (idx >> 5) & 15;
    int p  = (idx >> 9) & 1023;
    int b  = idx >> 19;

    size_t base = (((size_t)(b * HH + h) * PSL) + p) * DH + d4 * 4;
    float4 kq = *(const float4*)&pk[(size_t)idx * 4];
    float4 vv = *(const float4*)&pv[(size_t)idx * 4];
    bsplit4_store(kq, g_Kh + base, g_Kl + base, 0);
    bsplit4_store(vv, g_Vh + base, g_Vl + base, 0);
}

// ---------------------------------------------------------------------------
// HMMA GEMM: 128x128 CTA tile, bf16-split (3 virtual K passes), cp.async
// double-buffered — R7 measured-best schedule (issue -> wait_group 1 ->
// barrier -> compute -> barrier), 1 CTA/SM.
//   mode 0: q (LoRA+RoPE+scale -> Qh/Ql)   mode 1: k (LoRA+RoPE -> Kh/Kl)
//   mode 2: v (LoRA -> Vh/Vl)              mode 3: o (LoRA -> Cout fp32)
// smem: A bufs [2][16384] at 0 | B bufs [2][16384] at 32768 | wBs at 67584
//   epilogue Cst fp32 [128][132] aliases buffers at 0
// ---------------------------------------------------------------------------
#define GEMM_SMEM (67584 + 8192 + 128)
#define NSTAGE 96

__global__ __launch_bounds__(256)
void gemm_tc(const float* __restrict__ psc,
             const float* __restrict__ fcos, const float* __restrict__ fsin,
             const float* __restrict__ Bq, const float* __restrict__ Bk,
             const float* __restrict__ Bv,
             float* __restrict__ Cout, int is_o)
{
    extern __shared__ __align__(128) char dsm[];
    const uint32_t smem_raw = smem_to_u32(dsm);
    const uint32_t sb = (smem_raw + 127) & ~127u;
    char* sgen = dsm + (sb - smem_raw);

    const int tid  = threadIdx.x;
    const int lane = tid & 31;
    const int w    = tid >> 5;
    const int mode = is_o ? 3 : blockIdx.z;
    const int m0   = blockIdx.y * 128;
    const int n0   = blockIdx.x * 128;

    const __nv_bfloat16* __restrict__ Ahi = is_o ? g_ahi : g_xhi;
    const __nv_bfloat16* __restrict__ Alo = is_o ? g_alo : g_xlo;
    const __nv_bfloat16* __restrict__ Bhi = g_whi + (size_t)mode * DD * DD;
    const __nv_bfloat16* __restrict__ Blo = g_wlo + (size_t)mode * DD * DD;

    // LoRA wB tile -> smem (region disjoint from mainloop tiles)
    float* wBs = (float*)(sgen + 67584);
    const float* wBp = (mode == 0 || mode == 3) ? Bq : ((mode == 1) ? Bk : Bv);
    for (int idx = tid; idx < 16 * 128; idx += 256)
        wBs[idx] = wBp[(idx >> 7) * DD + n0 + (idx & 127)];

    const int rb = tid >> 3;
    const int c8 = tid & 7;
    const uint32_t dx   = (uint32_t)((c8 ^ (rb & 7)) * 16);
    const uint32_t drow = (uint32_t)(rb * 128);

    const int wm = (w & 1) * 64;
    const int wn = (w >> 1) * 32;
    const int lrow = lane & 15;
    const uint32_t lcol = (uint32_t)((lane >> 4) * 16);
    uint32_t arow[4], amask[4], brow[2], bmask[2];
#pragma unroll
    for (int i = 0; i < 4; i++) {
        int rr = wm + i * 16 + lrow;
        arow[i] = (uint32_t)(rr * 128); amask[i] = (uint32_t)((rr & 7) * 16);
    }
#pragma unroll
    for (int jj = 0; jj < 2; jj++) {
        int rr = wn + jj * 16 + lrow;
        brow[jj] = (uint32_t)(rr * 128); bmask[jj] = (uint32_t)((rr & 7) * 16);
    }

    float d[4][4][4];
#pragma unroll
    for (int i = 0; i < 4; i++)
#pragma unroll
        for (int j = 0; j < 4; j++)
#pragma unroll
            for (int q = 0; q < 4; q++) d[i][j][q] = 0.f;

    auto issue = [&](int s) {
        const int buf = s & 1;
        const int ko  = (s & 31) << 6;
        const __nv_bfloat16* As = (s >= 64) ? Alo : Ahi;
        const __nv_bfloat16* Bs = (s >= 32 && s < 64) ? Blo : Bhi;
        const __nv_bfloat16* ap = As + (size_t)(m0 + rb) * DD + ko + c8 * 8;
        const __nv_bfloat16* bp = Bs + (size_t)(n0 + rb) * DD + ko + c8 * 8;
        const uint32_t da = sb + (uint32_t)(buf * 16384) + drow + dx;
        const uint32_t db = sb + 32768u + (uint32_t)(buf * 16384) + drow + dx;
#pragma unroll
        for (int t = 0; t < 4; t++) {
            cp16(da + t * 32 * 128, ap + (size_t)t * 32 * DD);
            cp16(db + t * 32 * 128, bp + (size_t)t * 32 * DD);
        }
        CP_COMMIT();
    };

    issue(0);
    for (int s = 0; s < NSTAGE; s++) {
        if (s + 1 < NSTAGE) { issue(s + 1); CP_WAIT1(); }
        else                { CP_WAIT0(); }
        __syncthreads();

        const uint32_t abase = sb + (uint32_t)((s & 1) * 16384);
        const uint32_t bbase = sb + 32768u + (uint32_t)((s & 1) * 16384);
#pragma unroll
        for (int kk = 0; kk < 4; kk++) {
            const uint32_t kb = (uint32_t)(kk * 32);
            uint32_t bf[4][2];
#pragma unroll
            for (int jj = 0; jj < 2; jj++) {
                uint32_t t4[4];
                ldsm4(t4, bbase + brow[jj] + ((kb + lcol) ^ bmask[jj]));
                bf[jj * 2][0]     = t4[0];
                bf[jj * 2 + 1][0] = t4[1];
                bf[jj * 2][1]     = t4[2];
                bf[jj * 2 + 1][1] = t4[3];
            }
            uint32_t af[4][4];
#pragma unroll
            for (int i = 0; i < 4; i++)
                ldsm4(af[i], abase + arow[i] + ((kb + lcol) ^ amask[i]));
#pragma unroll
            for (int i = 0; i < 4; i++)
#pragma unroll
                for (int j = 0; j < 4; j++)
                    mma16816(d[i][j], af[i], bf[j]);
        }
        __syncthreads();
    }

    // --- stage C into smem (stride 132) ---
    float* Cst = (float*)sgen;
    {
        const int qr = lane >> 2;
        const int qc = (lane & 3) * 2;
#pragma unroll
        for (int i = 0; i < 4; i++) {
#pragma unroll
            for (int j = 0; j < 4; j++) {
                int r0 = wm + i * 16 + qr;
                int cc = wn + j * 8 + qc;
                *(float2*)&Cst[r0 * 132 + cc]       = make_float2(d[i][j][0], d[i][j][1]);
                *(float2*)&Cst[(r0 + 8) * 132 + cc] = make_float2(d[i][j][2], d[i][j][3]);
            }
        }
    }
    __syncthreads();

    // --- per-row epilogue ---
    {
        const int row = tid >> 1;
        const int ch  = (tid & 1) * 64;
        const int m   = m0 + row;
        const int b   = m >> 11, sq = m & 2047;
        const float ps = psc[b];
        float aLv[16];
#pragma unroll
        for (int r = 0; r < 16; r++) {
            float sum = 0.f;
            if (is_o) {
                size_t o = (size_t)m * 16 + r;
#pragma unroll
                for (int p = 0; p < LKS; p++) sum += g_lo_part[p][o];
            } else {
                size_t o = (size_t)m * 48 + mode * 16 + r;
#pragma unroll
                for (int p = 0; p < LKS; p++) sum += g_lqkv_part[p][o];
            }
            aLv[r] = sum * ps;
        }

        const int h = n0 >> 7;
        // 1/sqrt(128) * log2(e): softmax runs in exp2 domain
        const float scl = 0.12751743645506170f;
#pragma unroll
        for (int half = 0; half < 2; half++) {
            const int cb = ch + half * 32;
            float c[32];
#pragma unroll
            for (int j = 0; j < 32; j++) {
                float lora = 0.f;
#pragma unroll
                for (int r = 0; r < 16; r++) lora += aLv[r] * wBs[r * 128 + cb + j];
                c[j] = Cst[row * 132 + cb + j] + lora;
            }
            if (mode == 3) {
                float* dst = &Cout[(size_t)m * DD + n0 + cb];
#pragma unroll
                for (int j = 0; j < 32; j += 4)
                    *(float4*)(dst + j) = make_float4(c[j], c[j+1], c[j+2], c[j+3]);
            } else if (mode == 2) {
                size_t off = (((size_t)(b * HH + h) * PSL) + PP + sq) * DH + cb;
                store32_split(c, g_Vh + off, g_Vl + off);
            } else {
                float v[32];
#pragma unroll
                for (int p = 0; p < 16; p++) {
                    int dcol = cb + 2 * p;
                    float cz = fcos[sq * 64 + (dcol >> 1)];
                    float sz = fsin[sq * 64 + (dcol >> 1)];
                    float a = c[2 * p], bq = c[2 * p + 1];
                    v[2 * p]     = a * cz - bq * sz;
                    v[2 * p + 1] = a * sz + bq * cz;
                }
                if (mode == 0) {
#pragma unroll
                    for (int j = 0; j < 32; j++) v[j] *= scl;
                    size_t off = (((size_t)(b * HH + h) * SS) + sq) * DH + cb;
                    store32_split(v, g_Qh + off, g_Ql + off);
                } else {
                    size_t off = (((size_t)(b * HH + h) * PSL) + PP + sq) * DH + cb;
                    store32_split(v, g_Kh + off, g_Kl + off);
                }
            }
        }
    }
}

// ---------------------------------------------------------------------------
// HMMA flash attention: 128-q CTA, 8 warps (16 q each), 64-key tiles,
// bf16 hi/lo split on Q/K and P/V, softmax in exp2 domain, one barrier/tile.
// smem: QH 0 | QL 32768 | stage s at 65536+s*65536: KH,KL,VH,VL (16KB each)
// ---------------------------------------------------------------------------
#define ATTN_SMEM (65536 + 2 * 65536)

__global__ __launch_bounds__(256, 1)
void attn_mma()
{
    extern __shared__ __align__(128) char smdyn[];
    const uint32_t sb = smem_to_u32(smdyn);

    const int tid  = threadIdx.x;
    const int lane = tid & 31;
    const int w    = tid >> 5;
    const int bh   = blockIdx.y;
    const int i0   = blockIdx.x * 128;

    const __nv_bfloat16* Qhp = g_Qh + ((size_t)bh * SS + i0) * DH;
    const __nv_bfloat16* Qlp = g_Ql + ((size_t)bh * SS + i0) * DH;
    const __nv_bfloat16* Khp = g_Kh + (size_t)bh * PSL * DH;
    const __nv_bfloat16* Klp = g_Kl + (size_t)bh * PSL * DH;
    const __nv_bfloat16* Vhp = g_Vh + (size_t)bh * PSL * DH;
    const __nv_bfloat16* Vlp = g_Vl + (size_t)bh * PSL * DH;

    // ---- Q tiles (hi+lo), one cp.async group ----
    {
        int row = tid >> 1, cg = tid & 1;
        const __nv_bfloat16* qh = Qhp + (size_t)row * DH;
        const __nv_bfloat16* ql = Qlp + (size_t)row * DH;
        uint32_t dst = sb + row * 256;
#pragma unroll
        for (int i = 0; i < 8; i++) {
            int c = cg * 8 + i;
            uint32_t so = (uint32_t)((c ^ (row & 7)) * 16);
            cp16(dst + so, qh + c * 8);
            cp16(dst + 32768 + so, ql + c * 8);
        }
    }
    CP_COMMIT();

    const int ntiles = 18 + (i0 >> 6);
    auto issue_kv = [&](int t) {
        int row = tid >> 2, cg = tid & 3, j0 = t * 64;
        size_t goff = (size_t)(j0 + row) * DH;
        uint32_t dst = sb + 65536u + (uint32_t)((t & 1) * 65536) + row * 256;
#pragma unroll
        for (int i = 0; i < 4; i++) {
            int c = cg * 4 + i;
            uint32_t so = (uint32_t)((c ^ (row & 7)) * 16);
            cp16(dst + so,          Khp + goff + c * 8);
            cp16(dst + 16384 + so,  Klp + goff + c * 8);
            cp16(dst + 32768 + so,  Vhp + goff + c * 8);
            cp16(dst + 49152 + so,  Vlp + goff + c * 8);
        }
        CP_COMMIT();
    };
    issue_kv(0);

    float o[16][4];
#pragma unroll
    for (int i = 0; i < 16; i++)
#pragma unroll
        for (int q = 0; q < 4; q++) o[i][q] = 0.f;
    float m0r = -1e30f, m1r = -1e30f, l0 = 0.f, l1 = 0.f;

    const int lrow = lane & 15;
    const int lh   = lane >> 4;
    const uint32_t qaddr = sb + (uint32_t)((w * 16 + lrow) * 256);
    const int qsw = (w * 16 + lrow) & 7;
    const int ksw = lrow & 7;
    const int lim0 = PP + i0 + w * 16 + (lane >> 2);

    for (int t = 0; t < ntiles; t++) {
        CP_WAIT0();            // tile t (and Q on t=0) landed
        __syncthreads();       // visibility + all warps done with buffer (t+1)&1
        if (t + 1 < ntiles) issue_kv(t + 1);

        const uint32_t KHb = sb + 65536u + (uint32_t)((t & 1) * 65536);

        // ---- S = Q K^T (3 split passes fused) ----
        float s[8][4];
#pragma unroll
        for (int na = 0; na < 8; na++)
#pragma unroll
            for (int q = 0; q < 4; q++) s[na][q] = 0.f;

#pragma unroll
        for (int kk = 0; kk < 8; kk++) {
            uint32_t afh[4], afl[4];
            uint32_t ca = (uint32_t)(((kk * 2 + lh) ^ qsw) * 16);
            ldsm4(afh, qaddr + ca);
            ldsm4(afl, qaddr + 32768 + ca);
            uint32_t ck = (uint32_t)(((kk * 2 + lh) ^ ksw) * 16);
#pragma unroll
            for (int nb = 0; nb < 4; nb++) {
                uint32_t raddr = KHb + (uint32_t)((nb * 16 + lrow) * 256) + ck;
                uint32_t tkh[4], tkl[4];
                ldsm4(tkh, raddr);
                ldsm4(tkl, raddr + 16384);
                uint32_t b0h[2] = {tkh[0], tkh[2]}, b1h[2] = {tkh[1], tkh[3]};
                uint32_t b0l[2] = {tkl[0], tkl[2]}, b1l[2] = {tkl[1], tkl[3]};
                mma16816(s[2 * nb],     afh, b0h);
                mma16816(s[2 * nb],     afh, b0l);
                mma16816(s[2 * nb],     afl, b0h);
                mma16816(s[2 * nb + 1], afh, b1h);
                mma16816(s[2 * nb + 1], afh, b1l);
                mma16816(s[2 * nb + 1], afl, b1h);
            }
        }

        // ---- mask (last two tiles only) ----
        const int j0 = t * 64;
        if (j0 + 63 > PP + i0) {
#pragma unroll
            for (int na = 0; na < 8; na++) {
                int j = j0 + na * 8 + (lane & 3) * 2;
                if (j > lim0)         s[na][0] = -1e30f;
                if (j + 1 > lim0)     s[na][1] = -1e30f;
                if (j > lim0 + 8)     s[na][2] = -1e30f;
                if (j + 1 > lim0 + 8) s[na][3] = -1e30f;
            }
        }

        // ---- online softmax in exp2 domain (log2e folded into Q scale) ----
        float mt0 = -1e30f, mt1 = -1e30f;
#pragma unroll
        for (int na = 0; na < 8; na++) {
            mt0 = fmaxf(mt0, fmaxf(s[na][0], s[na][1]));
            mt1 = fmaxf(mt1, fmaxf(s[na][2], s[na][3]));
        }
        mt0 = fmaxf(mt0, __shfl_xor_sync(0xffffffffu, mt0, 1));
        mt0 = fmaxf(mt0, __shfl_xor_sync(0xffffffffu, mt0, 2));
        mt1 = fmaxf(mt1, __shfl_xor_sync(0xffffffffu, mt1, 1));
        mt1 = fmaxf(mt1, __shfl_xor_sync(0xffffffffu, mt1, 2));
        float mn0 = fmaxf(m0r, mt0), mn1 = fmaxf(m1r, mt1);
        float a0 = ex2f(m0r - mn0), a1 = ex2f(m1r - mn1);
        m0r = mn0; m1r = mn1;
        float s0 = 0.f, s1 = 0.f;
#pragma unroll
        for (int na = 0; na < 8; na++) {
            s[na][0] = ex2f(s[na][0] - mn0); s0 += s[na][0];
            s[na][1] = ex2f(s[na][1] - mn0); s0 += s[na][1];
            s[na][2] = ex2f(s[na][2] - mn1); s1 += s[na][2];
            s[na][3] = ex2f(s[na][3] - mn1); s1 += s[na][3];
        }
        s0 += __shfl_xor_sync(0xffffffffu, s0, 1);
        s0 += __shfl_xor_sync(0xffffffffu, s0, 2);
        s1 += __shfl_xor_sync(0xffffffffu, s1, 1);
        s1 += __shfl_xor_sync(0xffffffffu, s1, 2);
        l0 = l0 * a0 + s0;
        l1 = l1 * a1 + s1;
#pragma unroll
        for (int na = 0; na < 16; na++) {
            o[na][0] *= a0; o[na][1] *= a0;
            o[na][2] *= a1; o[na][3] *= a1;
        }

        // ---- O += P V (P from registers, 3 split passes) ----
        const uint32_t VHb = KHb + 32768u;
#pragma unroll
        for (int jj = 0; jj < 4; jj++) {
            uint32_t ph[4], pl[4];
            bfsplit2(s[2 * jj][0],     s[2 * jj][1],     ph[0], pl[0]);
            bfsplit2(s[2 * jj][2],     s[2 * jj][3],     ph[1], pl[1]);
            bfsplit2(s[2 * jj + 1][0], s[2 * jj + 1][1], ph[2], pl[2]);
            bfsplit2(s[2 * jj + 1][2], s[2 * jj + 1][3], ph[3], pl[3]);
#pragma unroll
            for (int db = 0; db < 8; db++) {
                uint32_t vaddr = VHb + (uint32_t)((jj * 16 + lrow) * 256)
                               + (uint32_t)(((db * 2 + lh) ^ ksw) * 16);
                uint32_t tvh[4], tvl[4];
                ldsm4t(tvh, vaddr);
                ldsm4t(tvl, vaddr + 16384);
                uint32_t bh0[2] = {tvh[0], tvh[1]}, bh1[2] = {tvh[2], tvh[3]};
                uint32_t bl0[2] = {tvl[0], tvl[1]}, bl1[2] = {tvl[2], tvl[3]};
                mma16816(o[2 * db],     ph, bh0);
                mma16816(o[2 * db],     pl, bh0);
                mma16816(o[2 * db],     ph, bl0);
                mma16816(o[2 * db + 1], ph, bh1);
                mma16816(o[2 * db + 1], pl, bh1);
                mma16816(o[2 * db + 1], ph, bl1);
            }
        }
    }

    // ---- normalize + write (fp32 g_attn and bf16 hi/lo for O gemm) ----
    {
        float inv0 = 1.0f / l0, inv1 = 1.0f / l1;
        int q0 = i0 + w * 16 + (lane >> 2);
        int b = bh >> 4, h = bh & 15;
        size_t base0 = ((size_t)b * SS + q0) * DD + h * DH + (lane & 3) * 2;
        size_t base1 = base0 + (size_t)8 * DD;
#pragma unroll
        for (int na = 0; na < 16; na++) {
            size_t o0 = base0 + na * 8;
            size_t o1 = base1 + na * 8;
            float f0 = o[na][0] * inv0, f1 = o[na][1] * inv0;
            float f2 = o[na][2] * inv1, f3 = o[na][3] * inv1;
            *(float2*)&g_attn[o0] = make_float2(f0, f1);
            *(float2*)&g_attn[o1] = make_float2(f2, f3);
            uint32_t h2, l2;
            bfsplit2(f0, f1, h2, l2);
            *(uint32_t*)&g_ahi[o0] = h2;
            *(uint32_t*)&g_alo[o0] = l2;
            bfsplit2(f2, f3, h2, l2);
            *(uint32_t*)&g_ahi[o1] = h2;
            *(uint32_t*)&g_alo[o1] = l2;
        }
    }
}

// ---------------------------------------------------------------------------
// Launch
// ---------------------------------------------------------------------------
extern "C" void kernel_launch(void* const* d_in, const int* in_sizes, int n_in,
                              void* d_out, int out_size)
{
    const float* x    = (const float*)d_in[0];
    const float* fcos = (const float*)d_in[1];
    const float* fsin = (const float*)d_in[2];
    // d_in[3] = mask (unused; causality computed analytically)
    const float* pk   = (const float*)d_in[4];
    const float* pv   = (const float*)d_in[5];
    const float* ps   = (const float*)d_in[6];
    const float* wq   = (const float*)d_in[7];
    const float* wk   = (const float*)d_in[8];
    const float* wv   = (const float*)d_in[9];
    const float* wo   = (const float*)d_in[10];
    const float* wqA  = (const float*)d_in[11];
    const float* wqB  = (const float*)d_in[12];
    const float* wkA  = (const float*)d_in[13];
    const float* wkB  = (const float*)d_in[14];
    const float* wvA  = (const float*)d_in[15];
    const float* wvB  = (const float*)d_in[16];
    const float* woA  = (const float*)d_in[17];
    const float* woB  = (const float*)d_in[18];
    float* out        = (float*)d_out;

    static void* sym_xhi = nullptr, *sym_xlo = nullptr;
    if (!sym_xhi) {
        cudaGetSymbolAddress(&sym_xhi, g_xhi);
        cudaGetSymbolAddress(&sym_xlo, g_xlo);
    }

    cudaFuncSetAttribute(gemm_tc, cudaFuncAttributeMaxDynamicSharedMemorySize,
                         GEMM_SMEM);
    cudaFuncSetAttribute(attn_mma, cudaFuncAttributeMaxDynamicSharedMemorySize,
                         ATTN_SMEM);

    scatter_prev<<<(BB * PP * HH * (DH / 4) + 255) / 256, 256>>>(pk, pv);
    split4<<<(MM * DD / 4) / 256, 256>>>(x, (__nv_bfloat16*)sym_xhi,
                                         (__nv_bfloat16*)sym_xlo);
    split_w4<<<dim3((DD * DD / 4) / 256, 1, 4), 256>>>(wq, wk, wv, wo);
    lora_down_qkv<<<dim3(MM / 64, LKS), 256>>>(x, wqA, wkA, wvA);

    gemm_tc<<<dim3(DD / 128, MM / 128, 3), 256, GEMM_SMEM>>>(
        ps, fcos, fsin, wqB, wkB, wvB, nullptr, 0);

    attn_mma<<<dim3(SS / 128, BB * HH), 256, ATTN_SMEM>>>();

    lora_down_o<<<dim3(MM / 64, LKS), 256>>>(woA);

    gemm_tc<<<dim3(DD / 128, MM / 128, 1), 256, GEMM_SMEM>>>(
        ps, fcos, fsin, woB, nullptr, nullptr, out, 1);
}

// round 15
// speedup vs baseline: 1.2154x; 1.1909x over previous
#include <cuda_runtime.h>
#include <cuda_bf16.h>
#include <cuda_fp16.h>
#include <cstdint>

typedef unsigned long long ull;

// Problem constants
#define BB   2
#define SS   2048
#define PP   1024
#define DD   2048
#define HH   16
#define DH   128
#define PSL  3072          // P + S
#define MM   4096          // B * S
#define LKS  8             // lora split-K factor

// ---------------------------------------------------------------------------
// Scratch (device globals; no allocation allowed in kernel_launch)
// ---------------------------------------------------------------------------
__device__ float g_attn[(size_t)MM * DD];             // [m, h*DH+d] fp32
__device__ float g_lqkv_part[LKS][(size_t)MM * 48];   // lora down partials (q|k|v)
__device__ float g_lo_part[LKS][(size_t)MM * 16];

// fp16 split operands for dense GEMMs (A split hi/lo, W rounded once)
__device__ __half g_xhi[(size_t)MM * DD];
__device__ __half g_xlo[(size_t)MM * DD];
__device__ __half g_ahi[(size_t)MM * DD];
__device__ __half g_alo[(size_t)MM * DD];
__device__ __half g_whi[(size_t)4 * DD * DD];         // wq|wk|wv|wo (fp16 RN)

// attention operands, bf16 hi/lo split (3-pass accuracy kept in attention)
__device__ __nv_bfloat16 g_Qh[(size_t)BB * HH * SS * DH];   // [b,h,s,d] (pre-scaled)
__device__ __nv_bfloat16 g_Ql[(size_t)BB * HH * SS * DH];
__device__ __nv_bfloat16 g_Kh[(size_t)BB * HH * PSL * DH];  // [b,h,j,d]
__device__ __nv_bfloat16 g_Kl[(size_t)BB * HH * PSL * DH];
__device__ __nv_bfloat16 g_Vh[(size_t)BB * HH * PSL * DH];  // [b,h,j,d]
__device__ __nv_bfloat16 g_Vl[(size_t)BB * HH * PSL * DH];

// ---------------------------------------------------------------------------
// helpers
// ---------------------------------------------------------------------------
__device__ __forceinline__ uint32_t smem_to_u32(const void* smem_ptr) {
    uint32_t addr;
    asm("{ .reg .u64 tmp; cvta.to.shared.u64 tmp, %1; cvt.u32.u64 %0, tmp; }"
        : "=r"(addr) : "l"(smem_ptr));
    return addr;
}
__device__ __forceinline__ void cp16(uint32_t dst, const void* src) {
    asm volatile("cp.async.cg.shared.global [%0], [%1], 16;"
                 :: "r"(dst), "l"(src) : "memory");
}
#define CP_COMMIT() asm volatile("cp.async.commit_group;" ::: "memory")
#define CP_WAIT1()  asm volatile("cp.async.wait_group 1;" ::: "memory")
#define CP_WAIT0()  asm volatile("cp.async.wait_group 0;" ::: "memory")

__device__ __forceinline__ void ldsm4(uint32_t a[4], uint32_t addr) {
    asm volatile("ldmatrix.sync.aligned.m8n8.x4.shared.b16 {%0,%1,%2,%3}, [%4];"
        : "=r"(a[0]), "=r"(a[1]), "=r"(a[2]), "=r"(a[3]) : "r"(addr));
}
__device__ __forceinline__ void ldsm4t(uint32_t a[4], uint32_t addr) {
    asm volatile("ldmatrix.sync.aligned.m8n8.x4.trans.shared.b16 {%0,%1,%2,%3}, [%4];"
        : "=r"(a[0]), "=r"(a[1]), "=r"(a[2]), "=r"(a[3]) : "r"(addr));
}
// bf16 mma (attention)
__device__ __forceinline__ void mma16816(float d[4], const uint32_t a[4],
                                         const uint32_t b[2]) {
    asm volatile(
        "mma.sync.aligned.m16n8k16.row.col.f32.bf16.bf16.f32 "
        "{%0,%1,%2,%3}, {%4,%5,%6,%7}, {%8,%9}, {%0,%1,%2,%3};"
        : "+f"(d[0]), "+f"(d[1]), "+f"(d[2]), "+f"(d[3])
        : "r"(a[0]), "r"(a[1]), "r"(a[2]), "r"(a[3]), "r"(b[0]), "r"(b[1]));
}
// fp16 mma (dense GEMMs)
__device__ __forceinline__ void mma16816h(float d[4], const uint32_t a[4],
                                          const uint32_t b[2]) {
    asm volatile(
        "mma.sync.aligned.m16n8k16.row.col.f32.f16.f16.f32 "
        "{%0,%1,%2,%3}, {%4,%5,%6,%7}, {%8,%9}, {%0,%1,%2,%3};"
        : "+f"(d[0]), "+f"(d[1]), "+f"(d[2]), "+f"(d[3])
        : "r"(a[0]), "r"(a[1]), "r"(a[2]), "r"(a[3]), "r"(b[0]), "r"(b[1]));
}
__device__ __forceinline__ float ex2f(float x) {
    float r; asm("ex2.approx.ftz.f32 %0, %1;" : "=f"(r) : "f"(x)); return r;
}

// --- bf16 truncation split (attention path) ---
__device__ __forceinline__ void bfsplit2(float a, float b, uint32_t& h, uint32_t& l) {
    uint32_t ai = __float_as_uint(a), bi = __float_as_uint(b);
    h = __byte_perm(ai, bi, 0x7632);
    float ra = a - __uint_as_float(ai & 0xffff0000u);
    float rb = b - __uint_as_float(bi & 0xffff0000u);
    asm("cvt.rn.bf16x2.f32 %0, %1, %2;" : "=r"(l) : "f"(rb), "f"(ra));
}
// split-store 32 consecutive floats as bf16 hi/lo (dst 16B-aligned)
__device__ __forceinline__ void store32_split(const float* v,
                                              __nv_bfloat16* dh, __nv_bfloat16* dl) {
    uint32_t hs[16], ls[16];
#pragma unroll
    for (int j = 0; j < 16; j++) bfsplit2(v[2 * j], v[2 * j + 1], hs[j], ls[j]);
#pragma unroll
    for (int j = 0; j < 4; j++) {
        ((uint4*)dh)[j] = *(uint4*)&hs[j * 4];
        ((uint4*)dl)[j] = *(uint4*)&ls[j * 4];
    }
}

// --- fp16 RN split (dense GEMM path): a in low half, b in high half ---
__device__ __forceinline__ void hsplit2(float a, float b, uint32_t& h, uint32_t& l) {
    asm("cvt.rn.f16x2.f32 %0, %1, %2;" : "=r"(h) : "f"(b), "f"(a));
    __half2 hh = *reinterpret_cast<__half2*>(&h);
    float ra = a - __low2float(hh);
    float rb = b - __high2float(hh);
    asm("cvt.rn.f16x2.f32 %0, %1, %2;" : "=r"(l) : "f"(rb), "f"(ra));
}
__device__ __forceinline__ uint32_t hpack2(float a, float b) {
    uint32_t h;
    asm("cvt.rn.f16x2.f32 %0, %1, %2;" : "=r"(h) : "f"(b), "f"(a));
    return h;
}

// ---------------------------------------------------------------------------
// fp32 -> split kernels
// ---------------------------------------------------------------------------
__device__ __forceinline__ void bsplit4_store(float4 v, __nv_bfloat16* hi,
                                              __nv_bfloat16* lo, size_t i4)
{
    uint32_t h0, l0, h1, l1;
    bfsplit2(v.x, v.y, h0, l0);
    bfsplit2(v.z, v.w, h1, l1);
    ((uint2*)hi)[i4] = make_uint2(h0, h1);
    ((uint2*)lo)[i4] = make_uint2(l0, l1);
}
__device__ __forceinline__ void hsplit4_store(float4 v, __half* hi,
                                              __half* lo, size_t i4)
{
    uint32_t h0, l0, h1, l1;
    hsplit2(v.x, v.y, h0, l0);
    hsplit2(v.z, v.w, h1, l1);
    ((uint2*)hi)[i4] = make_uint2(h0, h1);
    ((uint2*)lo)[i4] = make_uint2(l0, l1);
}

__global__ __launch_bounds__(256)
void split4(const float* __restrict__ src, __half* __restrict__ hi,
            __half* __restrict__ lo)
{
    size_t i = (size_t)blockIdx.x * 256 + threadIdx.x;
    float4 v = ((const float4*)src)[i];
    hsplit4_store(v, hi, lo, i);
}

// weights: single fp16 RN (no lo)
__global__ __launch_bounds__(256)
void split_w4(const float* __restrict__ w0, const float* __restrict__ w1,
              const float* __restrict__ w2, const float* __restrict__ w3)
{
    const int z = blockIdx.z;
    const float* src = (z == 0) ? w0 : ((z == 1) ? w1 : ((z == 2) ? w2 : w3));
    __half* hi = g_whi + (size_t)z * DD * DD;
    size_t i = (size_t)blockIdx.x * 256 + threadIdx.x;
    float4 v = ((const float4*)src)[i];
    ((uint2*)hi)[i] = make_uint2(hpack2(v.x, v.y), hpack2(v.z, v.w));
}

// ---------------------------------------------------------------------------
// LoRA down-projections: split-K=LKS, thread = 4 rows x 3 cols (qkv) / 4x1 (o)
// ---------------------------------------------------------------------------
__global__ __launch_bounds__(256)
void lora_down_qkv(const float* __restrict__ x,
                   const float* __restrict__ wqA,
                   const float* __restrict__ wkA,
                   const float* __restrict__ wvA)
{
    __shared__ float xs[32][68];
    __shared__ float ws[32][48];
    const int tid = threadIdx.x;
    const int m0  = blockIdx.x * 64;
    const int kq  = blockIdx.y;
    const int cg  = tid & 15;
    const int rg  = tid >> 4;
    const int KSEG = DD / LKS;            // 256

    float acc[4][3];
#pragma unroll
    for (int i = 0; i < 4; i++)
#pragma unroll
        for (int j = 0; j < 3; j++) acc[i][j] = 0.f;

    const int srow = tid >> 2, seg = tid & 3;
    for (int k0 = kq * KSEG; k0 < kq * KSEG + KSEG; k0 += 32) {
        const float* xp = &x[(size_t)(m0 + srow) * DD + k0 + seg * 8];
        float4 v0 = *(const float4*)xp;
        float4 v1 = *(const float4*)(xp + 4);
        const int sbk = seg * 8;
        xs[sbk + 0][srow] = v0.x; xs[sbk + 1][srow] = v0.y;
        xs[sbk + 2][srow] = v0.z; xs[sbk + 3][srow] = v0.w;
        xs[sbk + 4][srow] = v1.x; xs[sbk + 5][srow] = v1.y;
        xs[sbk + 6][srow] = v1.z; xs[sbk + 7][srow] = v1.w;
        for (int idx = tid; idx < 32 * 48; idx += 256) {
            int kk = idx / 48, c = idx % 48;
            const float* w = (c < 16) ? wqA : ((c < 32) ? wkA : wvA);
            ws[kk][c] = w[(size_t)(k0 + kk) * 16 + (c & 15)];
        }
        __syncthreads();
#pragma unroll
        for (int kk = 0; kk < 32; kk++) {
            float4 xv = *(const float4*)&xs[kk][rg * 4];
            float w0 = ws[kk][cg * 3 + 0];
            float w1 = ws[kk][cg * 3 + 1];
            float w2 = ws[kk][cg * 3 + 2];
            acc[0][0] += xv.x * w0; acc[0][1] += xv.x * w1; acc[0][2] += xv.x * w2;
            acc[1][0] += xv.y * w0; acc[1][1] += xv.y * w1; acc[1][2] += xv.y * w2;
            acc[2][0] += xv.z * w0; acc[2][1] += xv.z * w1; acc[2][2] += xv.z * w2;
            acc[3][0] += xv.w * w0; acc[3][1] += xv.w * w1; acc[3][2] += xv.w * w2;
        }
        __syncthreads();
    }
#pragma unroll
    for (int i = 0; i < 4; i++)
#pragma unroll
        for (int j = 0; j < 3; j++)
            g_lqkv_part[kq][(size_t)(m0 + rg * 4 + i) * 48 + cg * 3 + j] = acc[i][j];
}

__global__ __launch_bounds__(256)
void lora_down_o(const float* __restrict__ woA)
{
    __shared__ float xs[32][68];
    __shared__ float ws[32][16];
    const int tid = threadIdx.x;
    const int m0  = blockIdx.x * 64;
    const int kq  = blockIdx.y;
    const int cg  = tid & 15;
    const int rg  = tid >> 4;
    const int KSEG = DD / LKS;

    float acc[4] = {0.f, 0.f, 0.f, 0.f};
    const int srow = tid >> 2, seg = tid & 3;
    for (int k0 = kq * KSEG; k0 < kq * KSEG + KSEG; k0 += 32) {
        const float* xp = &g_attn[(size_t)(m0 + srow) * DD + k0 + seg * 8];
        float4 v0 = *(const float4*)xp;
        float4 v1 = *(const float4*)(xp + 4);
        const int sbk = seg * 8;
        xs[sbk + 0][srow] = v0.x; xs[sbk + 1][srow] = v0.y;
        xs[sbk + 2][srow] = v0.z; xs[sbk + 3][srow] = v0.w;
        xs[sbk + 4][srow] = v1.x; xs[sbk + 5][srow] = v1.y;
        xs[sbk + 6][srow] = v1.z; xs[sbk + 7][srow] = v1.w;
        for (int idx = tid; idx < 32 * 16; idx += 256) {
            int kk = idx >> 4, c = idx & 15;
            ws[kk][c] = woA[(size_t)(k0 + kk) * 16 + c];
        }
        __syncthreads();
#pragma unroll
        for (int kk = 0; kk < 32; kk++) {
            float4 xv = *(const float4*)&xs[kk][rg * 4];
            float w0 = ws[kk][cg];
            acc[0] += xv.x * w0; acc[1] += xv.y * w0;
            acc[2] += xv.z * w0; acc[3] += xv.w * w0;
        }
        __syncthreads();
    }
#pragma unroll
    for (int i = 0; i < 4; i++)
        g_lo_part[kq][(size_t)(m0 + rg * 4 + i) * 16 + cg] = acc[i];
}

// ---------------------------------------------------------------------------
// scatter prev_key/prev_value into bf16 hi/lo attention layouts
// ---------------------------------------------------------------------------
__global__ void scatter_prev(const float* __restrict__ pk, const float* __restrict__ pv)
{
    int idx = blockIdx.x * blockDim.x + threadIdx.x;   // over B*P*H*(DH/4)
    if (idx >= BB * PP * HH * (DH / 4)) return;
    int d4 = idx & 31;
    int h  = (idx >> 5) & 15;
    int p  = (idx >> 9) & 1023;
    int b  = idx >> 19;

    size_t base = (((size_t)(b * HH + h) * PSL) + p) * DH + d4 * 4;
    float4 kq = *(const float4*)&pk[(size_t)idx * 4];
    float4 vv = *(const float4*)&pv[(size_t)idx * 4];
    bsplit4_store(kq, g_Kh + base, g_Kl + base, 0);
    bsplit4_store(vv, g_Vh + base, g_Vl + base, 0);
}

// ---------------------------------------------------------------------------
// HMMA GEMM: 128x128 CTA tile, fp16 2-pass split (A=hi then A=lo, W fp16-RN),
// cp.async double-buffered — R7 measured-best schedule, 1 CTA/SM.
//   mode 0: q (LoRA+RoPE+scale -> Qh/Ql)   mode 1: k (LoRA+RoPE -> Kh/Kl)
//   mode 2: v (LoRA -> Vh/Vl)              mode 3: o (LoRA -> Cout fp32)
// smem: A bufs [2][16384] at 0 | B bufs [2][16384] at 32768 | wBs at 67584
//   epilogue Cst fp32 [128][132] aliases buffers at 0
// ---------------------------------------------------------------------------
#define GEMM_SMEM (67584 + 8192 + 128)
#define NSTAGE 64

__global__ __launch_bounds__(256)
void gemm_tc(const float* __restrict__ psc,
             const float* __restrict__ fcos, const float* __restrict__ fsin,
             const float* __restrict__ Bq, const float* __restrict__ Bk,
             const float* __restrict__ Bv,
             float* __restrict__ Cout, int is_o)
{
    extern __shared__ __align__(128) char dsm[];
    const uint32_t smem_raw = smem_to_u32(dsm);
    const uint32_t sb = (smem_raw + 127) & ~127u;
    char* sgen = dsm + (sb - smem_raw);

    const int tid  = threadIdx.x;
    const int lane = tid & 31;
    const int w    = tid >> 5;
    const int mode = is_o ? 3 : blockIdx.z;
    const int m0   = blockIdx.y * 128;
    const int n0   = blockIdx.x * 128;

    const __half* __restrict__ Ahi = is_o ? g_ahi : g_xhi;
    const __half* __restrict__ Alo = is_o ? g_alo : g_xlo;
    const __half* __restrict__ Bhi = g_whi + (size_t)mode * DD * DD;

    // LoRA wB tile -> smem (region disjoint from mainloop tiles)
    float* wBs = (float*)(sgen + 67584);
    const float* wBp = (mode == 0 || mode == 3) ? Bq : ((mode == 1) ? Bk : Bv);
    for (int idx = tid; idx < 16 * 128; idx += 256)
        wBs[idx] = wBp[(idx >> 7) * DD + n0 + (idx & 127)];

    const int rb = tid >> 3;
    const int c8 = tid & 7;
    const uint32_t dx   = (uint32_t)((c8 ^ (rb & 7)) * 16);
    const uint32_t drow = (uint32_t)(rb * 128);

    const int wm = (w & 1) * 64;
    const int wn = (w >> 1) * 32;
    const int lrow = lane & 15;
    const uint32_t lcol = (uint32_t)((lane >> 4) * 16);
    uint32_t arow[4], amask[4], brow[2], bmask[2];
#pragma unroll
    for (int i = 0; i < 4; i++) {
        int rr = wm + i * 16 + lrow;
        arow[i] = (uint32_t)(rr * 128); amask[i] = (uint32_t)((rr & 7) * 16);
    }
#pragma unroll
    for (int jj = 0; jj < 2; jj++) {
        int rr = wn + jj * 16 + lrow;
        brow[jj] = (uint32_t)(rr * 128); bmask[jj] = (uint32_t)((rr & 7) * 16);
    }

    float d[4][4][4];
#pragma unroll
    for (int i = 0; i < 4; i++)
#pragma unroll
        for (int j = 0; j < 4; j++)
#pragma unroll
            for (int q = 0; q < 4; q++) d[i][j][q] = 0.f;

    auto issue = [&](int s) {
        const int buf = s & 1;
        const int ko  = (s & 31) << 6;
        const __half* As = (s >= 32) ? Alo : Ahi;   // pass 0: A-hi, pass 1: A-lo
        const __half* Bs = Bhi;                     // W always fp16-RN
        const __half* ap = As + (size_t)(m0 + rb) * DD + ko + c8 * 8;
        const __half* bp = Bs + (size_t)(n0 + rb) * DD + ko + c8 * 8;
        const uint32_t da = sb + (uint32_t)(buf * 16384) + drow + dx;
        const uint32_t db = sb + 32768u + (uint32_t)(buf * 16384) + drow + dx;
#pragma unroll
        for (int t = 0; t < 4; t++) {
            cp16(da + t * 32 * 128, ap + (size_t)t * 32 * DD);
            cp16(db + t * 32 * 128, bp + (size_t)t * 32 * DD);
        }
        CP_COMMIT();
    };

    issue(0);
    for (int s = 0; s < NSTAGE; s++) {
        if (s + 1 < NSTAGE) { issue(s + 1); CP_WAIT1(); }
        else                { CP_WAIT0(); }
        __syncthreads();

        const uint32_t abase = sb + (uint32_t)((s & 1) * 16384);
        const uint32_t bbase = sb + 32768u + (uint32_t)((s & 1) * 16384);
#pragma unroll
        for (int kk = 0; kk < 4; kk++) {
            const uint32_t kb = (uint32_t)(kk * 32);
            uint32_t bf[4][2];
#pragma unroll
            for (int jj = 0; jj < 2; jj++) {
                uint32_t t4[4];
                ldsm4(t4, bbase + brow[jj] + ((kb + lcol) ^ bmask[jj]));
                bf[jj * 2][0]     = t4[0];
                bf[jj * 2 + 1][0] = t4[1];
                bf[jj * 2][1]     = t4[2];
                bf[jj * 2 + 1][1] = t4[3];
            }
            uint32_t af[4][4];
#pragma unroll
            for (int i = 0; i < 4; i++)
                ldsm4(af[i], abase + arow[i] + ((kb + lcol) ^ amask[i]));
#pragma unroll
            for (int i = 0; i < 4; i++)
#pragma unroll
                for (int j = 0; j < 4; j++)
                    mma16816h(d[i][j], af[i], bf[j]);
        }
        __syncthreads();
    }

    // --- stage C into smem (stride 132) ---
    float* Cst = (float*)sgen;
    {
        const int qr = lane >> 2;
        const int qc = (lane & 3) * 2;
#pragma unroll
        for (int i = 0; i < 4; i++) {
#pragma unroll
            for (int j = 0; j < 4; j++) {
                int r0 = wm + i * 16 + qr;
                int cc = wn + j * 8 + qc;
                *(float2*)&Cst[r0 * 132 + cc]       = make_float2(d[i][j][0], d[i][j][1]);
                *(float2*)&Cst[(r0 + 8) * 132 + cc] = make_float2(d[i][j][2], d[i][j][3]);
            }
        }
    }
    __syncthreads();

    // --- per-row epilogue ---
    {
        const int row = tid >> 1;
        const int ch  = (tid & 1) * 64;
        const int m   = m0 + row;
        const int b   = m >> 11, sq = m & 2047;
        const float ps = psc[b];
        float aLv[16];
#pragma unroll
        for (int r = 0; r < 16; r++) {
            float sum = 0.f;
            if (is_o) {
                size_t o = (size_t)m * 16 + r;
#pragma unroll
                for (int p = 0; p < LKS; p++) sum += g_lo_part[p][o];
            } else {
                size_t o = (size_t)m * 48 + mode * 16 + r;
#pragma unroll
                for (int p = 0; p < LKS; p++) sum += g_lqkv_part[p][o];
            }
            aLv[r] = sum * ps;
        }

        const int h = n0 >> 7;
        // 1/sqrt(128) * log2(e): softmax runs in exp2 domain
        const float scl = 0.12751743645506170f;
#pragma unroll
        for (int half = 0; half < 2; half++) {
            const int cb = ch + half * 32;
            float c[32];
#pragma unroll
            for (int j = 0; j < 32; j++) {
                float lora = 0.f;
#pragma unroll
                for (int r = 0; r < 16; r++) lora += aLv[r] * wBs[r * 128 + cb + j];
                c[j] = Cst[row * 132 + cb + j] + lora;
            }
            if (mode == 3) {
                float* dst = &Cout[(size_t)m * DD + n0 + cb];
#pragma unroll
                for (int j = 0; j < 32; j += 4)
                    *(float4*)(dst + j) = make_float4(c[j], c[j+1], c[j+2], c[j+3]);
            } else if (mode == 2) {
                size_t off = (((size_t)(b * HH + h) * PSL) + PP + sq) * DH + cb;
                store32_split(c, g_Vh + off, g_Vl + off);
            } else {
                float v[32];
#pragma unroll
                for (int p = 0; p < 16; p++) {
                    int dcol = cb + 2 * p;
                    float cz = fcos[sq * 64 + (dcol >> 1)];
                    float sz = fsin[sq * 64 + (dcol >> 1)];
                    float a = c[2 * p], bq = c[2 * p + 1];
                    v[2 * p]     = a * cz - bq * sz;
                    v[2 * p + 1] = a * sz + bq * cz;
                }
                if (mode == 0) {
#pragma unroll
                    for (int j = 0; j < 32; j++) v[j] *= scl;
                    size_t off = (((size_t)(b * HH + h) * SS) + sq) * DH + cb;
                    store32_split(v, g_Qh + off, g_Ql + off);
                } else {
                    size_t off = (((size_t)(b * HH + h) * PSL) + PP + sq) * DH + cb;
                    store32_split(v, g_Kh + off, g_Kl + off);
                }
            }
        }
    }
}

// ---------------------------------------------------------------------------
// HMMA flash attention: 128-q CTA, 8 warps (16 q each), 64-key tiles,
// bf16 hi/lo split on Q/K and P/V, softmax in exp2 domain, one barrier/tile.
// smem: QH 0 | QL 32768 | stage s at 65536+s*65536: KH,KL,VH,VL (16KB each)
// ---------------------------------------------------------------------------
#define ATTN_SMEM (65536 + 2 * 65536)

__global__ __launch_bounds__(256, 1)
void attn_mma()
{
    extern __shared__ __align__(128) char smdyn[];
    const uint32_t sb = smem_to_u32(smdyn);

    const int tid  = threadIdx.x;
    const int lane = tid & 31;
    const int w    = tid >> 5;
    const int bh   = blockIdx.y;
    const int i0   = blockIdx.x * 128;

    const __nv_bfloat16* Qhp = g_Qh + ((size_t)bh * SS + i0) * DH;
    const __nv_bfloat16* Qlp = g_Ql + ((size_t)bh * SS + i0) * DH;
    const __nv_bfloat16* Khp = g_Kh + (size_t)bh * PSL * DH;
    const __nv_bfloat16* Klp = g_Kl + (size_t)bh * PSL * DH;
    const __nv_bfloat16* Vhp = g_Vh + (size_t)bh * PSL * DH;
    const __nv_bfloat16* Vlp = g_Vl + (size_t)bh * PSL * DH;

    // ---- Q tiles (hi+lo), one cp.async group ----
    {
        int row = tid >> 1, cg = tid & 1;
        const __nv_bfloat16* qh = Qhp + (size_t)row * DH;
        const __nv_bfloat16* ql = Qlp + (size_t)row * DH;
        uint32_t dst = sb + row * 256;
#pragma unroll
        for (int i = 0; i < 8; i++) {
            int c = cg * 8 + i;
            uint32_t so = (uint32_t)((c ^ (row & 7)) * 16);
            cp16(dst + so, qh + c * 8);
            cp16(dst + 32768 + so, ql + c * 8);
        }
    }
    CP_COMMIT();

    const int ntiles = 18 + (i0 >> 6);
    auto issue_kv = [&](int t) {
        int row = tid >> 2, cg = tid & 3, j0 = t * 64;
        size_t goff = (size_t)(j0 + row) * DH;
        uint32_t dst = sb + 65536u + (uint32_t)((t & 1) * 65536) + row * 256;
#pragma unroll
        for (int i = 0; i < 4; i++) {
            int c = cg * 4 + i;
            uint32_t so = (uint32_t)((c ^ (row & 7)) * 16);
            cp16(dst + so,          Khp + goff + c * 8);
            cp16(dst + 16384 + so,  Klp + goff + c * 8);
            cp16(dst + 32768 + so,  Vhp + goff + c * 8);
            cp16(dst + 49152 + so,  Vlp + goff + c * 8);
        }
        CP_COMMIT();
    };
    issue_kv(0);

    float o[16][4];
#pragma unroll
    for (int i = 0; i < 16; i++)
#pragma unroll
        for (int q = 0; q < 4; q++) o[i][q] = 0.f;
    float m0r = -1e30f, m1r = -1e30f, l0 = 0.f, l1 = 0.f;

    const int lrow = lane & 15;
    const int lh   = lane >> 4;
    const uint32_t qaddr = sb + (uint32_t)((w * 16 + lrow) * 256);
    const int qsw = (w * 16 + lrow) & 7;
    const int ksw = lrow & 7;
    const int lim0 = PP + i0 + w * 16 + (lane >> 2);

    for (int t = 0; t < ntiles; t++) {
        CP_WAIT0();            // tile t (and Q on t=0) landed
        __syncthreads();       // visibility + all warps done with buffer (t+1)&1
        if (t + 1 < ntiles) issue_kv(t + 1);

        const uint32_t KHb = sb + 65536u + (uint32_t)((t & 1) * 65536);

        // ---- S = Q K^T (3 split passes fused) ----
        float s[8][4];
#pragma unroll
        for (int na = 0; na < 8; na++)
#pragma unroll
            for (int q = 0; q < 4; q++) s[na][q] = 0.f;

#pragma unroll
        for (int kk = 0; kk < 8; kk++) {
            uint32_t afh[4], afl[4];
            uint32_t ca = (uint32_t)(((kk * 2 + lh) ^ qsw) * 16);
            ldsm4(afh, qaddr + ca);
            ldsm4(afl, qaddr + 32768 + ca);
            uint32_t ck = (uint32_t)(((kk * 2 + lh) ^ ksw) * 16);
#pragma unroll
            for (int nb = 0; nb < 4; nb++) {
                uint32_t raddr = KHb + (uint32_t)((nb * 16 + lrow) * 256) + ck;
                uint32_t tkh[4], tkl[4];
                ldsm4(tkh, raddr);
                ldsm4(tkl, raddr + 16384);
                uint32_t b0h[2] = {tkh[0], tkh[2]}, b1h[2] = {tkh[1], tkh[3]};
                uint32_t b0l[2] = {tkl[0], tkl[2]}, b1l[2] = {tkl[1], tkl[3]};
                mma16816(s[2 * nb],     afh, b0h);
                mma16816(s[2 * nb],     afh, b0l);
                mma16816(s[2 * nb],     afl, b0h);
                mma16816(s[2 * nb + 1], afh, b1h);
                mma16816(s[2 * nb + 1], afh, b1l);
                mma16816(s[2 * nb + 1], afl, b1h);
            }
        }

        // ---- mask (last two tiles only) ----
        const int j0 = t * 64;
        if (j0 + 63 > PP + i0) {
#pragma unroll
            for (int na = 0; na < 8; na++) {
                int j = j0 + na * 8 + (lane & 3) * 2;
                if (j > lim0)         s[na][0] = -1e30f;
                if (j + 1 > lim0)     s[na][1] = -1e30f;
                if (j > lim0 + 8)     s[na][2] = -1e30f;
                if (j + 1 > lim0 + 8) s[na][3] = -1e30f;
            }
        }

        // ---- online softmax in exp2 domain (log2e folded into Q scale) ----
        float mt0 = -1e30f, mt1 = -1e30f;
#pragma unroll
        for (int na = 0; na < 8; na++) {
            mt0 = fmaxf(mt0, fmaxf(s[na][0], s[na][1]));
            mt1 = fmaxf(mt1, fmaxf(s[na][2], s[na][3]));
        }
        mt0 = fmaxf(mt0, __shfl_xor_sync(0xffffffffu, mt0, 1));
        mt0 = fmaxf(mt0, __shfl_xor_sync(0xffffffffu, mt0, 2));
        mt1 = fmaxf(mt1, __shfl_xor_sync(0xffffffffu, mt1, 1));
        mt1 = fmaxf(mt1, __shfl_xor_sync(0xffffffffu, mt1, 2));
        float mn0 = fmaxf(m0r, mt0), mn1 = fmaxf(m1r, mt1);
        float a0 = ex2f(m0r - mn0), a1 = ex2f(m1r - mn1);
        m0r = mn0; m1r = mn1;
        float s0 = 0.f, s1 = 0.f;
#pragma unroll
        for (int na = 0; na < 8; na++) {
            s[na][0] = ex2f(s[na][0] - mn0); s0 += s[na][0];
            s[na][1] = ex2f(s[na][1] - mn0); s0 += s[na][1];
            s[na][2] = ex2f(s[na][2] - mn1); s1 += s[na][2];
            s[na][3] = ex2f(s[na][3] - mn1); s1 += s[na][3];
        }
        s0 += __shfl_xor_sync(0xffffffffu, s0, 1);
        s0 += __shfl_xor_sync(0xffffffffu, s0, 2);
        s1 += __shfl_xor_sync(0xffffffffu, s1, 1);
        s1 += __shfl_xor_sync(0xffffffffu, s1, 2);
        l0 = l0 * a0 + s0;
        l1 = l1 * a1 + s1;
#pragma unroll
        for (int na = 0; na < 16; na++) {
            o[na][0] *= a0; o[na][1] *= a0;
            o[na][2] *= a1; o[na][3] *= a1;
        }

        // ---- O += P V (P from registers, 3 split passes) ----
        const uint32_t VHb = KHb + 32768u;
#pragma unroll
        for (int jj = 0; jj < 4; jj++) {
            uint32_t ph[4], pl[4];
            bfsplit2(s[2 * jj][0],     s[2 * jj][1],     ph[0], pl[0]);
            bfsplit2(s[2 * jj][2],     s[2 * jj][3],     ph[1], pl[1]);
            bfsplit2(s[2 * jj + 1][0], s[2 * jj + 1][1], ph[2], pl[2]);
            bfsplit2(s[2 * jj + 1][2], s[2 * jj + 1][3], ph[3], pl[3]);
#pragma unroll
            for (int db = 0; db < 8; db++) {
                uint32_t vaddr = VHb + (uint32_t)((jj * 16 + lrow) * 256)
                               + (uint32_t)(((db * 2 + lh) ^ ksw) * 16);
                uint32_t tvh[4], tvl[4];
                ldsm4t(tvh, vaddr);
                ldsm4t(tvl, vaddr + 16384);
                uint32_t bh0[2] = {tvh[0], tvh[1]}, bh1[2] = {tvh[2], tvh[3]};
                uint32_t bl0[2] = {tvl[0], tvl[1]}, bl1[2] = {tvl[2], tvl[3]};
                mma16816(o[2 * db],     ph, bh0);
                mma16816(o[2 * db],     pl, bh0);
                mma16816(o[2 * db],     ph, bl0);
                mma16816(o[2 * db + 1], ph, bh1);
                mma16816(o[2 * db + 1], pl, bh1);
                mma16816(o[2 * db + 1], ph, bl1);
            }
        }
    }

    // ---- normalize + write (fp32 g_attn and fp16 hi/lo for O gemm) ----
    {
        float inv0 = 1.0f / l0, inv1 = 1.0f / l1;
        int q0 = i0 + w * 16 + (lane >> 2);
        int b = bh >> 4, h = bh & 15;
        size_t base0 = ((size_t)b * SS + q0) * DD + h * DH + (lane & 3) * 2;
        size_t base1 = base0 + (size_t)8 * DD;
#pragma unroll
        for (int na = 0; na < 16; na++) {
            size_t o0 = base0 + na * 8;
            size_t o1 = base1 + na * 8;
            float f0 = o[na][0] * inv0, f1 = o[na][1] * inv0;
            float f2 = o[na][2] * inv1, f3 = o[na][3] * inv1;
            *(float2*)&g_attn[o0] = make_float2(f0, f1);
            *(float2*)&g_attn[o1] = make_float2(f2, f3);
            uint32_t h2, l2;
            hsplit2(f0, f1, h2, l2);
            *(uint32_t*)&g_ahi[o0] = h2;
            *(uint32_t*)&g_alo[o0] = l2;
            hsplit2(f2, f3, h2, l2);
            *(uint32_t*)&g_ahi[o1] = h2;
            *(uint32_t*)&g_alo[o1] = l2;
        }
    }
}

// ---------------------------------------------------------------------------
// Launch
// ---------------------------------------------------------------------------
extern "C" void kernel_launch(void* const* d_in, const int* in_sizes, int n_in,
                              void* d_out, int out_size)
{
    const float* x    = (const float*)d_in[0];
    const float* fcos = (const float*)d_in[1];
    const float* fsin = (const float*)d_in[2];
    // d_in[3] = mask (unused; causality computed analytically)
    const float* pk   = (const float*)d_in[4];
    const float* pv   = (const float*)d_in[5];
    const float* ps   = (const float*)d_in[6];
    const float* wq   = (const float*)d_in[7];
    const float* wk   = (const float*)d_in[8];
    const float* wv   = (const float*)d_in[9];
    const float* wo   = (const float*)d_in[10];
    const float* wqA  = (const float*)d_in[11];
    const float* wqB  = (const float*)d_in[12];
    const float* wkA  = (const float*)d_in[13];
    const float* wkB  = (const float*)d_in[14];
    const float* wvA  = (const float*)d_in[15];
    const float* wvB  = (const float*)d_in[16];
    const float* woA  = (const float*)d_in[17];
    const float* woB  = (const float*)d_in[18];
    float* out        = (float*)d_out;

    static void* sym_xhi = nullptr, *sym_xlo = nullptr;
    if (!sym_xhi) {
        cudaGetSymbolAddress(&sym_xhi, g_xhi);
        cudaGetSymbolAddress(&sym_xlo, g_xlo);
    }

    cudaFuncSetAttribute(gemm_tc, cudaFuncAttributeMaxDynamicSharedMemorySize,
                         GEMM_SMEM);
    cudaFuncSetAttribute(attn_mma, cudaFuncAttributeMaxDynamicSharedMemorySize,
                         ATTN_SMEM);

    scatter_prev<<<(BB * PP * HH * (DH / 4) + 255) / 256, 256>>>(pk, pv);
    split4<<<(MM * DD / 4) / 256, 256>>>(x, (__half*)sym_xhi, (__half*)sym_xlo);
    split_w4<<<dim3((DD * DD / 4) / 256, 1, 4), 256>>>(wq, wk, wv, wo);
    lora_down_qkv<<<dim3(MM / 64, LKS), 256>>>(x, wqA, wkA, wvA);

    gemm_tc<<<dim3(DD / 128, MM / 128, 3), 256, GEMM_SMEM>>>(
        ps, fcos, fsin, wqB, wkB, wvB, nullptr, 0);

    attn_mma<<<dim3(SS / 128, BB * HH), 256, ATTN_SMEM>>>();

    lora_down_o<<<dim3(MM / 64, LKS), 256>>>(woA);

    gemm_tc<<<dim3(DD / 128, MM / 128, 1), 256, GEMM_SMEM>>>(
        ps, fcos, fsin, woB, nullptr, nullptr, out, 1);
}

// round 17
// speedup vs baseline: 1.4025x; 1.1539x over previous
#include <cuda_runtime.h>
#include <cuda_bf16.h>
#include <cuda_fp16.h>
#include <cstdint>

typedef unsigned long long ull;

// Problem constants
#define BB   2
#define SS   2048
#define PP   1024
#define DD   2048
#define HH   16
#define DH   128
#define PSL  3072          // P + S
#define MM   4096          // B * S
#define LKS  8             // lora split-K factor

// ---------------------------------------------------------------------------
// Scratch (device globals; no allocation allowed in kernel_launch)
// ---------------------------------------------------------------------------
__device__ float g_attn[(size_t)MM * DD];             // [m, h*DH+d] fp32
__device__ float g_lqkv_part[LKS][(size_t)MM * 48];   // lora down partials (q|k|v)
__device__ float g_lo_part[LKS][(size_t)MM * 16];

// fp16 split operands for dense GEMMs (A split hi/lo, W rounded once)
__device__ __half g_xhi[(size_t)MM * DD];
__device__ __half g_xlo[(size_t)MM * DD];
__device__ __half g_ahi[(size_t)MM * DD];
__device__ __half g_alo[(size_t)MM * DD];
__device__ __half g_whi[(size_t)4 * DD * DD];         // wq|wk|wv|wo (fp16 RN)

// attention operands (fp16): Q split hi/lo (exact), K/V rounded once
__device__ __half g_Qh[(size_t)BB * HH * SS * DH];    // [b,h,s,d] (pre-scaled)
__device__ __half g_Ql[(size_t)BB * HH * SS * DH];
__device__ __half g_K16[(size_t)BB * HH * PSL * DH];  // [b,h,j,d]
__device__ __half g_V16[(size_t)BB * HH * PSL * DH];  // [b,h,j,d]

// ---------------------------------------------------------------------------
// helpers
// ---------------------------------------------------------------------------
__device__ __forceinline__ uint32_t smem_to_u32(const void* smem_ptr) {
    uint32_t addr;
    asm("{ .reg .u64 tmp; cvta.to.shared.u64 tmp, %1; cvt.u32.u64 %0, tmp; }"
        : "=r"(addr) : "l"(smem_ptr));
    return addr;
}
__device__ __forceinline__ void cp16(uint32_t dst, const void* src) {
    asm volatile("cp.async.cg.shared.global [%0], [%1], 16;"
                 :: "r"(dst), "l"(src) : "memory");
}
#define CP_COMMIT() asm volatile("cp.async.commit_group;" ::: "memory")
#define CP_WAIT1()  asm volatile("cp.async.wait_group 1;" ::: "memory")
#define CP_WAIT0()  asm volatile("cp.async.wait_group 0;" ::: "memory")

__device__ __forceinline__ void ldsm4(uint32_t a[4], uint32_t addr) {
    asm volatile("ldmatrix.sync.aligned.m8n8.x4.shared.b16 {%0,%1,%2,%3}, [%4];"
        : "=r"(a[0]), "=r"(a[1]), "=r"(a[2]), "=r"(a[3]) : "r"(addr));
}
__device__ __forceinline__ void ldsm4t(uint32_t a[4], uint32_t addr) {
    asm volatile("ldmatrix.sync.aligned.m8n8.x4.trans.shared.b16 {%0,%1,%2,%3}, [%4];"
        : "=r"(a[0]), "=r"(a[1]), "=r"(a[2]), "=r"(a[3]) : "r"(addr));
}
// fp16 mma
__device__ __forceinline__ void mma16816h(float d[4], const uint32_t a[4],
                                          const uint32_t b[2]) {
    asm volatile(
        "mma.sync.aligned.m16n8k16.row.col.f32.f16.f16.f32 "
        "{%0,%1,%2,%3}, {%4,%5,%6,%7}, {%8,%9}, {%0,%1,%2,%3};"
        : "+f"(d[0]), "+f"(d[1]), "+f"(d[2]), "+f"(d[3])
        : "r"(a[0]), "r"(a[1]), "r"(a[2]), "r"(a[3]), "r"(b[0]), "r"(b[1]));
}
__device__ __forceinline__ float ex2f(float x) {
    float r; asm("ex2.approx.ftz.f32 %0, %1;" : "=f"(r) : "f"(x)); return r;
}

// --- fp16 RN split: a in low half, b in high half ---
__device__ __forceinline__ void hsplit2(float a, float b, uint32_t& h, uint32_t& l) {
    asm("cvt.rn.f16x2.f32 %0, %1, %2;" : "=r"(h) : "f"(b), "f"(a));
    __half2 hh = *reinterpret_cast<__half2*>(&h);
    float ra = a - __low2float(hh);
    float rb = b - __high2float(hh);
    asm("cvt.rn.f16x2.f32 %0, %1, %2;" : "=r"(l) : "f"(rb), "f"(ra));
}
__device__ __forceinline__ uint32_t hpack2(float a, float b) {
    uint32_t h;
    asm("cvt.rn.f16x2.f32 %0, %1, %2;" : "=r"(h) : "f"(b), "f"(a));
    return h;
}
// store 32 consecutive floats as fp16 hi/lo pairs (dst 16B-aligned)
__device__ __forceinline__ void store32_split_h(const float* v,
                                                __half* dh, __half* dl) {
    uint32_t hs[16], ls[16];
#pragma unroll
    for (int j = 0; j < 16; j++) hsplit2(v[2 * j], v[2 * j + 1], hs[j], ls[j]);
#pragma unroll
    for (int j = 0; j < 4; j++) {
        ((uint4*)dh)[j] = *(uint4*)&hs[j * 4];
        ((uint4*)dl)[j] = *(uint4*)&ls[j * 4];
    }
}
// store 32 consecutive floats as single fp16 RN (dst 16B-aligned)
__device__ __forceinline__ void store32_h(const float* v, __half* d) {
    uint32_t hs[16];
#pragma unroll
    for (int j = 0; j < 16; j++) hs[j] = hpack2(v[2 * j], v[2 * j + 1]);
#pragma unroll
    for (int j = 0; j < 4; j++) ((uint4*)d)[j] = *(uint4*)&hs[j * 4];
}

// ---------------------------------------------------------------------------
// fp32 -> split kernels
// ---------------------------------------------------------------------------
__device__ __forceinline__ void hsplit4_store(float4 v, __half* hi,
                                              __half* lo, size_t i4)
{
    uint32_t h0, l0, h1, l1;
    hsplit2(v.x, v.y, h0, l0);
    hsplit2(v.z, v.w, h1, l1);
    ((uint2*)hi)[i4] = make_uint2(h0, h1);
    ((uint2*)lo)[i4] = make_uint2(l0, l1);
}

__global__ __launch_bounds__(256)
void split4(const float* __restrict__ src, __half* __restrict__ hi,
            __half* __restrict__ lo)
{
    size_t i = (size_t)blockIdx.x * 256 + threadIdx.x;
    float4 v = ((const float4*)src)[i];
    hsplit4_store(v, hi, lo, i);
}

// weights: single fp16 RN (no lo)
__global__ __launch_bounds__(256)
void split_w4(const float* __restrict__ w0, const float* __restrict__ w1,
              const float* __restrict__ w2, const float* __restrict__ w3)
{
    const int z = blockIdx.z;
    const float* src = (z == 0) ? w0 : ((z == 1) ? w1 : ((z == 2) ? w2 : w3));
    __half* hi = g_whi + (size_t)z * DD * DD;
    size_t i = (size_t)blockIdx.x * 256 + threadIdx.x;
    float4 v = ((const float4*)src)[i];
    ((uint2*)hi)[i] = make_uint2(hpack2(v.x, v.y), hpack2(v.z, v.w));
}

// ---------------------------------------------------------------------------
// LoRA down-projections: split-K=LKS, thread = 4 rows x 3 cols (qkv) / 4x1 (o)
// ---------------------------------------------------------------------------
__global__ __launch_bounds__(256)
void lora_down_qkv(const float* __restrict__ x,
                   const float* __restrict__ wqA,
                   const float* __restrict__ wkA,
                   const float* __restrict__ wvA)
{
    __shared__ float xs[32][68];
    __shared__ float ws[32][48];
    const int tid = threadIdx.x;
    const int m0  = blockIdx.x * 64;
    const int kq  = blockIdx.y;
    const int cg  = tid & 15;
    const int rg  = tid >> 4;
    const int KSEG = DD / LKS;            // 256

    float acc[4][3];
#pragma unroll
    for (int i = 0; i < 4; i++)
#pragma unroll
        for (int j = 0; j < 3; j++) acc[i][j] = 0.f;

    const int srow = tid >> 2, seg = tid & 3;
    for (int k0 = kq * KSEG; k0 < kq * KSEG + KSEG; k0 += 32) {
        const float* xp = &x[(size_t)(m0 + srow) * DD + k0 + seg * 8];
        float4 v0 = *(const float4*)xp;
        float4 v1 = *(const float4*)(xp + 4);
        const int sbk = seg * 8;
        xs[sbk + 0][srow] = v0.x; xs[sbk + 1][srow] = v0.y;
        xs[sbk + 2][srow] = v0.z; xs[sbk + 3][srow] = v0.w;
        xs[sbk + 4][srow] = v1.x; xs[sbk + 5][srow] = v1.y;
        xs[sbk + 6][srow] = v1.z; xs[sbk + 7][srow] = v1.w;
        for (int idx = tid; idx < 32 * 48; idx += 256) {
            int kk = idx / 48, c = idx % 48;
            const float* w = (c < 16) ? wqA : ((c < 32) ? wkA : wvA);
            ws[kk][c] = w[(size_t)(k0 + kk) * 16 + (c & 15)];
        }
        __syncthreads();
#pragma unroll
        for (int kk = 0; kk < 32; kk++) {
            float4 xv = *(const float4*)&xs[kk][rg * 4];
            float w0 = ws[kk][cg * 3 + 0];
            float w1 = ws[kk][cg * 3 + 1];
            float w2 = ws[kk][cg * 3 + 2];
            acc[0][0] += xv.x * w0; acc[0][1] += xv.x * w1; acc[0][2] += xv.x * w2;
            acc[1][0] += xv.y * w0; acc[1][1] += xv.y * w1; acc[1][2] += xv.y * w2;
            acc[2][0] += xv.z * w0; acc[2][1] += xv.z * w1; acc[2][2] += xv.z * w2;
            acc[3][0] += xv.w * w0; acc[3][1] += xv.w * w1; acc[3][2] += xv.w * w2;
        }
        __syncthreads();
    }
#pragma unroll
    for (int i = 0; i < 4; i++)
#pragma unroll
        for (int j = 0; j < 3; j++)
            g_lqkv_part[kq][(size_t)(m0 + rg * 4 + i) * 48 + cg * 3 + j] = acc[i][j];
}

__global__ __launch_bounds__(256)
void lora_down_o(const float* __restrict__ woA)
{
    __shared__ float xs[32][68];
    __shared__ float ws[32][16];
    const int tid = threadIdx.x;
    const int m0  = blockIdx.x * 64;
    const int kq  = blockIdx.y;
    const int cg  = tid & 15;
    const int rg  = tid >> 4;
    const int KSEG = DD / LKS;

    float acc[4] = {0.f, 0.f, 0.f, 0.f};
    const int srow = tid >> 2, seg = tid & 3;
    for (int k0 = kq * KSEG; k0 < kq * KSEG + KSEG; k0 += 32) {
        const float* xp = &g_attn[(size_t)(m0 + srow) * DD + k0 + seg * 8];
        float4 v0 = *(const float4*)xp;
        float4 v1 = *(const float4*)(xp + 4);
        const int sbk = seg * 8;
        xs[sbk + 0][srow] = v0.x; xs[sbk + 1][srow] = v0.y;
        xs[sbk + 2][srow] = v0.z; xs[sbk + 3][srow] = v0.w;
        xs[sbk + 4][srow] = v1.x; xs[sbk + 5][srow] = v1.y;
        xs[sbk + 6][srow] = v1.z; xs[sbk + 7][srow] = v1.w;
        for (int idx = tid; idx < 32 * 16; idx += 256) {
            int kk = idx >> 4, c = idx & 15;
            ws[kk][c] = woA[(size_t)(k0 + kk) * 16 + c];
        }
        __syncthreads();
#pragma unroll
        for (int kk = 0; kk < 32; kk++) {
            float4 xv = *(const float4*)&xs[kk][rg * 4];
            float w0 = ws[kk][cg];
            acc[0] += xv.x * w0; acc[1] += xv.y * w0;
            acc[2] += xv.z * w0; acc[3] += xv.w * w0;
        }
        __syncthreads();
    }
#pragma unroll
    for (int i = 0; i < 4; i++)
        g_lo_part[kq][(size_t)(m0 + rg * 4 + i) * 16 + cg] = acc[i];
}

// ---------------------------------------------------------------------------
// scatter prev_key/prev_value into fp16 attention layouts
// ---------------------------------------------------------------------------
__global__ void scatter_prev(const float* __restrict__ pk, const float* __restrict__ pv)
{
    int idx = blockIdx.x * blockDim.x + threadIdx.x;   // over B*P*H*(DH/4)
    if (idx >= BB * PP * HH * (DH / 4)) return;
    int d4 = idx & 31;
    int h  = (idx >> 5) & 15;
    int p  = (idx >> 9) & 1023;
    int b  = idx >> 19;

    size_t base = (((size_t)(b * HH + h) * PSL) + p) * DH + d4 * 4;
    float4 kq = *(const float4*)&pk[(size_t)idx * 4];
    float4 vv = *(const float4*)&pv[(size_t)idx * 4];
    ((uint2*)(g_K16 + base))[0] = make_uint2(hpack2(kq.x, kq.y), hpack2(kq.z, kq.w));
    ((uint2*)(g_V16 + base))[0] = make_uint2(hpack2(vv.x, vv.y), hpack2(vv.z, vv.w));
}

// ---------------------------------------------------------------------------
// HMMA GEMM: 128x128 CTA tile, fp16 2-pass split (A=hi then A=lo, W fp16-RN),
// cp.async double-buffered — R7 measured-best schedule, 1 CTA/SM.
//   mode 0: q (LoRA+RoPE+scale -> Qh/Ql fp16)   mode 1: k (LoRA+RoPE -> K16)
//   mode 2: v (LoRA -> V16)                     mode 3: o (LoRA -> Cout fp32)
// smem: A bufs [2][16384] at 0 | B bufs [2][16384] at 32768 | wBs at 67584
//   epilogue Cst fp32 [128][132] aliases buffers at 0
// ---------------------------------------------------------------------------
#define GEMM_SMEM (67584 + 8192 + 128)
#define NSTAGE 64

__global__ __launch_bounds__(256)
void gemm_tc(const float* __restrict__ psc,
             const float* __restrict__ fcos, const float* __restrict__ fsin,
             const float* __restrict__ Bq, const float* __restrict__ Bk,
             const float* __restrict__ Bv,
             float* __restrict__ Cout, int is_o)
{
    extern __shared__ __align__(128) char dsm[];
    const uint32_t smem_raw = smem_to_u32(dsm);
    const uint32_t sb = (smem_raw + 127) & ~127u;
    char* sgen = dsm + (sb - smem_raw);

    const int tid  = threadIdx.x;
    const int lane = tid & 31;
    const int w    = tid >> 5;
    const int mode = is_o ? 3 : blockIdx.z;
    const int m0   = blockIdx.y * 128;
    const int n0   = blockIdx.x * 128;

    const __half* __restrict__ Ahi = is_o ? g_ahi : g_xhi;
    const __half* __restrict__ Alo = is_o ? g_alo : g_xlo;
    const __half* __restrict__ Bhi = g_whi + (size_t)mode * DD * DD;

    // LoRA wB tile -> smem (region disjoint from mainloop tiles)
    float* wBs = (float*)(sgen + 67584);
    const float* wBp = (mode == 0 || mode == 3) ? Bq : ((mode == 1) ? Bk : Bv);
    for (int idx = tid; idx < 16 * 128; idx += 256)
        wBs[idx] = wBp[(idx >> 7) * DD + n0 + (idx & 127)];

    const int rb = tid >> 3;
    const int c8 = tid & 7;
    const uint32_t dx   = (uint32_t)((c8 ^ (rb & 7)) * 16);
    const uint32_t drow = (uint32_t)(rb * 128);

    const int wm = (w & 1) * 64;
    const int wn = (w >> 1) * 32;
    const int lrow = lane & 15;
    const uint32_t lcol = (uint32_t)((lane >> 4) * 16);
    uint32_t arow[4], amask[4], brow[2], bmask[2];
#pragma unroll
    for (int i = 0; i < 4; i++) {
        int rr = wm + i * 16 + lrow;
        arow[i] = (uint32_t)(rr * 128); amask[i] = (uint32_t)((rr & 7) * 16);
    }
#pragma unroll
    for (int jj = 0; jj < 2; jj++) {
        int rr = wn + jj * 16 + lrow;
        brow[jj] = (uint32_t)(rr * 128); bmask[jj] = (uint32_t)((rr & 7) * 16);
    }

    float d[4][4][4];
#pragma unroll
    for (int i = 0; i < 4; i++)
#pragma unroll
        for (int j = 0; j < 4; j++)
#pragma unroll
            for (int q = 0; q < 4; q++) d[i][j][q] = 0.f;

    auto issue = [&](int s) {
        const int buf = s & 1;
        const int ko  = (s & 31) << 6;
        const __half* As = (s >= 32) ? Alo : Ahi;   // pass 0: A-hi, pass 1: A-lo
        const __half* ap = As + (size_t)(m0 + rb) * DD + ko + c8 * 8;
        const __half* bp = Bhi + (size_t)(n0 + rb) * DD + ko + c8 * 8;
        const uint32_t da = sb + (uint32_t)(buf * 16384) + drow + dx;
        const uint32_t db = sb + 32768u + (uint32_t)(buf * 16384) + drow + dx;
#pragma unroll
        for (int t = 0; t < 4; t++) {
            cp16(da + t * 32 * 128, ap + (size_t)t * 32 * DD);
            cp16(db + t * 32 * 128, bp + (size_t)t * 32 * DD);
        }
        CP_COMMIT();
    };

    issue(0);
    for (int s = 0; s < NSTAGE; s++) {
        if (s + 1 < NSTAGE) { issue(s + 1); CP_WAIT1(); }
        else                { CP_WAIT0(); }
        __syncthreads();

        const uint32_t abase = sb + (uint32_t)((s & 1) * 16384);
        const uint32_t bbase = sb + 32768u + (uint32_t)((s & 1) * 16384);
#pragma unroll
        for (int kk = 0; kk < 4; kk++) {
            const uint32_t kb = (uint32_t)(kk * 32);
            uint32_t bf[4][2];
#pragma unroll
            for (int jj = 0; jj < 2; jj++) {
                uint32_t t4[4];
                ldsm4(t4, bbase + brow[jj] + ((kb + lcol) ^ bmask[jj]));
                bf[jj * 2][0]     = t4[0];
                bf[jj * 2 + 1][0] = t4[1];
                bf[jj * 2][1]     = t4[2];
                bf[jj * 2 + 1][1] = t4[3];
            }
            uint32_t af[4][4];
#pragma unroll
            for (int i = 0; i < 4; i++)
                ldsm4(af[i], abase + arow[i] + ((kb + lcol) ^ amask[i]));
#pragma unroll
            for (int i = 0; i < 4; i++)
#pragma unroll
                for (int j = 0; j < 4; j++)
                    mma16816h(d[i][j], af[i], bf[j]);
        }
        __syncthreads();
    }

    // --- stage C into smem (stride 132) ---
    float* Cst = (float*)sgen;
    {
        const int qr = lane >> 2;
        const int qc = (lane & 3) * 2;
#pragma unroll
        for (int i = 0; i < 4; i++) {
#pragma unroll
            for (int j = 0; j < 4; j++) {
                int r0 = wm + i * 16 + qr;
                int cc = wn + j * 8 + qc;
                *(float2*)&Cst[r0 * 132 + cc]       = make_float2(d[i][j][0], d[i][j][1]);
                *(float2*)&Cst[(r0 + 8) * 132 + cc] = make_float2(d[i][j][2], d[i][j][3]);
            }
        }
    }
    __syncthreads();

    // --- per-row epilogue ---
    {
        const int row = tid >> 1;
        const int ch  = (tid & 1) * 64;
        const int m   = m0 + row;
        const int b   = m >> 11, sq = m & 2047;
        const float ps = psc[b];
        float aLv[16];
#pragma unroll
        for (int r = 0; r < 16; r++) {
            float sum = 0.f;
            if (is_o) {
                size_t o = (size_t)m * 16 + r;
#pragma unroll
                for (int p = 0; p < LKS; p++) sum += g_lo_part[p][o];
            } else {
                size_t o = (size_t)m * 48 + mode * 16 + r;
#pragma unroll
                for (int p = 0; p < LKS; p++) sum += g_lqkv_part[p][o];
            }
            aLv[r] = sum * ps;
        }

        const int h = n0 >> 7;
        // 1/sqrt(128) * log2(e): softmax runs in exp2 domain
        const float scl = 0.12751743645506170f;
#pragma unroll
        for (int half = 0; half < 2; half++) {
            const int cb = ch + half * 32;
            float c[32];
#pragma unroll
            for (int j = 0; j < 32; j++) {
                float lora = 0.f;
#pragma unroll
                for (int r = 0; r < 16; r++) lora += aLv[r] * wBs[r * 128 + cb + j];
                c[j] = Cst[row * 132 + cb + j] + lora;
            }
            if (mode == 3) {
                float* dst = &Cout[(size_t)m * DD + n0 + cb];
#pragma unroll
                for (int j = 0; j < 32; j += 4)
                    *(float4*)(dst + j) = make_float4(c[j], c[j+1], c[j+2], c[j+3]);
            } else if (mode == 2) {
                size_t off = (((size_t)(b * HH + h) * PSL) + PP + sq) * DH + cb;
                store32_h(c, g_V16 + off);
            } else {
                float v[32];
#pragma unroll
                for (int p = 0; p < 16; p++) {
                    int dcol = cb + 2 * p;
                    float cz = fcos[sq * 64 + (dcol >> 1)];
                    float sz = fsin[sq * 64 + (dcol >> 1)];
                    float a = c[2 * p], bq = c[2 * p + 1];
                    v[2 * p]     = a * cz - bq * sz;
                    v[2 * p + 1] = a * sz + bq * cz;
                }
                if (mode == 0) {
#pragma unroll
                    for (int j = 0; j < 32; j++) v[j] *= scl;
                    size_t off = (((size_t)(b * HH + h) * SS) + sq) * DH + cb;
                    store32_split_h(v, g_Qh + off, g_Ql + off);
                } else {
                    size_t off = (((size_t)(b * HH + h) * PSL) + PP + sq) * DH + cb;
                    store32_h(v, g_K16 + off);
                }
            }
        }
    }
}

// ---------------------------------------------------------------------------
// HMMA flash attention (fp16): 128-q CTA, 8 warps (16 q each), 64-key tiles.
// S = (Qh+Ql)·K16 (2 passes), O = (Ph+Pl)·V16 (2 passes), exp2 softmax,
// one barrier/tile. smem: QH 0 | QL 32768 | stage s at 65536+s*32768:
//   K16 at +0 (16KB), V16 at +16384 (16KB)
// ---------------------------------------------------------------------------
#define ATTN_SMEM (65536 + 2 * 32768)

__global__ __launch_bounds__(256, 1)
void attn_mma()
{
    extern __shared__ __align__(128) char smdyn[];
    const uint32_t sb = smem_to_u32(smdyn);

    const int tid  = threadIdx.x;
    const int lane = tid & 31;
    const int w    = tid >> 5;
    const int bh   = blockIdx.y;
    const int i0   = blockIdx.x * 128;

    const __half* Qhp = g_Qh + ((size_t)bh * SS + i0) * DH;
    const __half* Qlp = g_Ql + ((size_t)bh * SS + i0) * DH;
    const __half* Kp  = g_K16 + (size_t)bh * PSL * DH;
    const __half* Vp  = g_V16 + (size_t)bh * PSL * DH;

    // ---- Q tiles (hi+lo), one cp.async group ----
    {
        int row = tid >> 1, cg = tid & 1;
        const __half* qh = Qhp + (size_t)row * DH;
        const __half* ql = Qlp + (size_t)row * DH;
        uint32_t dst = sb + row * 256;
#pragma unroll
        for (int i = 0; i < 8; i++) {
            int c = cg * 8 + i;
            uint32_t so = (uint32_t)((c ^ (row & 7)) * 16);
            cp16(dst + so, qh + c * 8);
            cp16(dst + 32768 + so, ql + c * 8);
        }
    }
    CP_COMMIT();

    const int ntiles = 18 + (i0 >> 6);
    auto issue_kv = [&](int t) {
        int row = tid >> 2, cg = tid & 3, j0 = t * 64;
        size_t goff = (size_t)(j0 + row) * DH;
        uint32_t dst = sb + 65536u + (uint32_t)((t & 1) * 32768) + row * 256;
#pragma unroll
        for (int i = 0; i < 4; i++) {
            int c = cg * 4 + i;
            uint32_t so = (uint32_t)((c ^ (row & 7)) * 16);
            cp16(dst + so,         Kp + goff + c * 8);
            cp16(dst + 16384 + so, Vp + goff + c * 8);
        }
        CP_COMMIT();
    };
    issue_kv(0);

    float o[16][4];
#pragma unroll
    for (int i = 0; i < 16; i++)
#pragma unroll
        for (int q = 0; q < 4; q++) o[i][q] = 0.f;
    float m0r = -1e30f, m1r = -1e30f, l0 = 0.f, l1 = 0.f;

    const int lrow = lane & 15;
    const int lh   = lane >> 4;
    const uint32_t qaddr = sb + (uint32_t)((w * 16 + lrow) * 256);
    const int qsw = (w * 16 + lrow) & 7;
    const int ksw = lrow & 7;
    const int lim0 = PP + i0 + w * 16 + (lane >> 2);

    for (int t = 0; t < ntiles; t++) {
        CP_WAIT0();            // tile t (and Q on t=0) landed
        __syncthreads();       // visibility + all warps done with buffer (t+1)&1
        if (t + 1 < ntiles) issue_kv(t + 1);

        const uint32_t KHb = sb + 65536u + (uint32_t)((t & 1) * 32768);

        // ---- S = (Qh+Ql) K16^T : 2 passes ----
        float s[8][4];
#pragma unroll
        for (int na = 0; na < 8; na++)
#pragma unroll
            for (int q = 0; q < 4; q++) s[na][q] = 0.f;

#pragma unroll
        for (int kk = 0; kk < 8; kk++) {
            uint32_t afh[4], afl[4];
            uint32_t ca = (uint32_t)(((kk * 2 + lh) ^ qsw) * 16);
            ldsm4(afh, qaddr + ca);
            ldsm4(afl, qaddr + 32768 + ca);
            uint32_t ck = (uint32_t)(((kk * 2 + lh) ^ ksw) * 16);
#pragma unroll
            for (int nb = 0; nb < 4; nb++) {
                uint32_t tk[4];
                ldsm4(tk, KHb + (uint32_t)((nb * 16 + lrow) * 256) + ck);
                uint32_t b0[2] = {tk[0], tk[2]}, b1[2] = {tk[1], tk[3]};
                mma16816h(s[2 * nb],     afh, b0);
                mma16816h(s[2 * nb],     afl, b0);
                mma16816h(s[2 * nb + 1], afh, b1);
                mma16816h(s[2 * nb + 1], afl, b1);
            }
        }

        // ---- mask (last two tiles only) ----
        const int j0 = t * 64;
        if (j0 + 63 > PP + i0) {
#pragma unroll
            for (int na = 0; na < 8; na++) {
                int j = j0 + na * 8 + (lane & 3) * 2;
                if (j > lim0)         s[na][0] = -1e30f;
                if (j + 1 > lim0)     s[na][1] = -1e30f;
                if (j > lim0 + 8)     s[na][2] = -1e30f;
                if (j + 1 > lim0 + 8) s[na][3] = -1e30f;
            }
        }

        // ---- online softmax in exp2 domain (log2e folded into Q scale) ----
        float mt0 = -1e30f, mt1 = -1e30f;
#pragma unroll
        for (int na = 0; na < 8; na++) {
            mt0 = fmaxf(mt0, fmaxf(s[na][0], s[na][1]));
            mt1 = fmaxf(mt1, fmaxf(s[na][2], s[na][3]));
        }
        mt0 = fmaxf(mt0, __shfl_xor_sync(0xffffffffu, mt0, 1));
        mt0 = fmaxf(mt0, __shfl_xor_sync(0xffffffffu, mt0, 2));
        mt1 = fmaxf(mt1, __shfl_xor_sync(0xffffffffu, mt1, 1));
        mt1 = fmaxf(mt1, __shfl_xor_sync(0xffffffffu, mt1, 2));
        float mn0 = fmaxf(m0r, mt0), mn1 = fmaxf(m1r, mt1);
        float a0 = ex2f(m0r - mn0), a1 = ex2f(m1r - mn1);
        m0r = mn0; m1r = mn1;
        float s0 = 0.f, s1 = 0.f;
#pragma unroll
        for (int na = 0; na < 8; na++) {
            s[na][0] = ex2f(s[na][0] - mn0); s0 += s[na][0];
            s[na][1] = ex2f(s[na][1] - mn0); s0 += s[na][1];
            s[na][2] = ex2f(s[na][2] - mn1); s1 += s[na][2];
            s[na][3] = ex2f(s[na][3] - mn1); s1 += s[na][3];
        }
        s0 += __shfl_xor_sync(0xffffffffu, s0, 1);
        s0 += __shfl_xor_sync(0xffffffffu, s0, 2);
        s1 += __shfl_xor_sync(0xffffffffu, s1, 1);
        s1 += __shfl_xor_sync(0xffffffffu, s1, 2);
        l0 = l0 * a0 + s0;
        l1 = l1 * a1 + s1;
#pragma unroll
        for (int na = 0; na < 16; na++) {
            o[na][0] *= a0; o[na][1] *= a0;
            o[na][2] *= a1; o[na][3] *= a1;
        }

        // ---- O += (Ph+Pl) V16 : 2 passes ----
        const uint32_t VHb = KHb + 16384u;
#pragma unroll
        for (int jj = 0; jj < 4; jj++) {
            uint32_t ph[4], pl[4];
            hsplit2(s[2 * jj][0],     s[2 * jj][1],     ph[0], pl[0]);
            hsplit2(s[2 * jj][2],     s[2 * jj][3],     ph[1], pl[1]);
            hsplit2(s[2 * jj + 1][0], s[2 * jj + 1][1], ph[2], pl[2]);
            hsplit2(s[2 * jj + 1][2], s[2 * jj + 1][3], ph[3], pl[3]);
#pragma unroll
            for (int db = 0; db < 8; db++) {
                uint32_t vaddr = VHb + (uint32_t)((jj * 16 + lrow) * 256)
                               + (uint32_t)(((db * 2 + lh) ^ ksw) * 16);
                uint32_t tv[4];
                ldsm4t(tv, vaddr);
                uint32_t bh0[2] = {tv[0], tv[1]}, bh1[2] = {tv[2], tv[3]};
                mma16816h(o[2 * db],     ph, bh0);
                mma16816h(o[2 * db],     pl, bh0);
                mma16816h(o[2 * db + 1], ph, bh1);
                mma16816h(o[2 * db + 1], pl, bh1);
            }
        }
    }

    // ---- normalize + write (fp32 g_attn and fp16 hi/lo for O gemm) ----
    {
        float inv0 = 1.0f / l0, inv1 = 1.0f / l1;
        int q0 = i0 + w * 16 + (lane >> 2);
        int b = bh >> 4, h = bh & 15;
        size_t base0 = ((size_t)b * SS + q0) * DD + h * DH + (lane & 3) * 2;
        size_t base1 = base0 + (size_t)8 * DD;
#pragma unroll
        for (int na = 0; na < 16; na++) {
            size_t o0 = base0 + na * 8;
            size_t o1 = base1 + na * 8;
            float f0 = o[na][0] * inv0, f1 = o[na][1] * inv0;
            float f2 = o[na][2] * inv1, f3 = o[na][3] * inv1;
            *(float2*)&g_attn[o0] = make_float2(f0, f1);
            *(float2*)&g_attn[o1] = make_float2(f2, f3);
            uint32_t h2, l2;
            hsplit2(f0, f1, h2, l2);
            *(uint32_t*)&g_ahi[o0] = h2;
            *(uint32_t*)&g_alo[o0] = l2;
            hsplit2(f2, f3, h2, l2);
            *(uint32_t*)&g_ahi[o1] = h2;
            *(uint32_t*)&g_alo[o1] = l2;
        }
    }
}

// ---------------------------------------------------------------------------
// Launch
// ---------------------------------------------------------------------------
extern "C" void kernel_launch(void* const* d_in, const int* in_sizes, int n_in,
                              void* d_out, int out_size)
{
    const float* x    = (const float*)d_in[0];
    const float* fcos = (const float*)d_in[1];
    const float* fsin = (const float*)d_in[2];
    // d_in[3] = mask (unused; causality computed analytically)
    const float* pk   = (const float*)d_in[4];
    const float* pv   = (const float*)d_in[5];
    const float* ps   = (const float*)d_in[6];
    const float* wq   = (const float*)d_in[7];
    const float* wk   = (const float*)d_in[8];
    const float* wv   = (const float*)d_in[9];
    const float* wo   = (const float*)d_in[10];
    const float* wqA  = (const float*)d_in[11];
    const float* wqB  = (const float*)d_in[12];
    const float* wkA  = (const float*)d_in[13];
    const float* wkB  = (const float*)d_in[14];
    const float* wvA  = (const float*)d_in[15];
    const float* wvB  = (const float*)d_in[16];
    const float* woA  = (const float*)d_in[17];
    const float* woB  = (const float*)d_in[18];
    float* out        = (float*)d_out;

    static void* sym_xhi = nullptr, *sym_xlo = nullptr;
    if (!sym_xhi) {
        cudaGetSymbolAddress(&sym_xhi, g_xhi);
        cudaGetSymbolAddress(&sym_xlo, g_xlo);
    }

    cudaFuncSetAttribute(gemm_tc, cudaFuncAttributeMaxDynamicSharedMemorySize,
                         GEMM_SMEM);
    cudaFuncSetAttribute(attn_mma, cudaFuncAttributeMaxDynamicSharedMemorySize,
                         ATTN_SMEM);

    scatter_prev<<<(BB * PP * HH * (DH / 4) + 255) / 256, 256>>>(pk, pv);
    split4<<<(MM * DD / 4) / 256, 256>>>(x, (__half*)sym_xhi, (__half*)sym_xlo);
    split_w4<<<dim3((DD * DD / 4) / 256, 1, 4), 256>>>(wq, wk, wv, wo);
    lora_down_qkv<<<dim3(MM / 64, LKS), 256>>>(x, wqA, wkA, wvA);

    gemm_tc<<<dim3(DD / 128, MM / 128, 3), 256, GEMM_SMEM>>>(
        ps, fcos, fsin, wqB, wkB, wvB, nullptr, 0);

    attn_mma<<<dim3(SS / 128, BB * HH), 256, ATTN_SMEM>>>();

    lora_down_o<<<dim3(MM / 64, LKS), 256>>>(woA);

    gemm_tc<<<dim3(DD / 128, MM / 128, 1), 256, GEMM_SMEM>>>(
        ps, fcos, fsin, woB, nullptr, nullptr, out, 1);
}